// round 1
// baseline (speedup 1.0000x reference)
#include <cuda_runtime.h>
#include <cstdint>
#include <cstdio>

// Problem constants (shapes fixed by setup_inputs)
#define NMAX  50000
#define F_IN  100
#define HID   128
#define H2D   64

// Single scratch arena: deg | invdeg | agg[N*128] | t1[N*128] | t2[N*64] | bn buffers
__device__ float g_scratch[NMAX * 2 + NMAX * 128 * 2 + NMAX * 64 + 768];

// ---------------------------------------------------------------------------
// utility kernels
// ---------------------------------------------------------------------------
__global__ void zero_kernel(float* __restrict__ p, int n) {
    int i = blockIdx.x * blockDim.x + threadIdx.x;
    for (; i < n; i += gridDim.x * blockDim.x) p[i] = 0.f;
}

__global__ void deg_kernel(const int* __restrict__ dst, float* __restrict__ deg, int E) {
    int e = blockIdx.x * blockDim.x + threadIdx.x;
    if (e < E) atomicAdd(&deg[dst[e]], 1.0f);
}

__global__ void invdeg_kernel(const float* __restrict__ deg, float* __restrict__ invdeg, int N) {
    int i = blockIdx.x * blockDim.x + threadIdx.x;
    if (i < N) invdeg[i] = 1.0f / fmaxf(deg[i], 1.0f);
}

// ---------------------------------------------------------------------------
// edge scatter: agg[dst] += x[src], vectorized 16B reduction atomics
// ---------------------------------------------------------------------------
template <int F4>
__global__ void scatter_kernel(const float4* __restrict__ x4,
                               const int* __restrict__ src,
                               const int* __restrict__ dst,
                               float* __restrict__ agg, int E) {
    int idx = blockIdx.x * blockDim.x + threadIdx.x;
    if (idx >= E * F4) return;
    int e = idx / F4;
    int g = idx - e * F4;
    int s = src[e];
    int d = dst[e];
    float4 v = x4[(size_t)s * F4 + g];
    float* p = agg + (size_t)d * (F4 * 4) + g * 4;
    asm volatile("red.global.add.v4.f32 [%0], {%1,%2,%3,%4};"
                 :: "l"(p), "f"(v.x), "f"(v.y), "f"(v.z), "f"(v.w)
                 : "memory");
}

// ---------------------------------------------------------------------------
// Tiled fp32 GEMM. Computes:
//   out[row, :] = act( (A1[row]*invdeg?[row]) @ Wl  +  A2[row] @ Wr  + bias )
// K2==0 => plain single-matrix GEMM. BM=64, BK=16, 256 threads, 4xTN microtile.
// ---------------------------------------------------------------------------
template <int K1, int K2, int NC, bool SCALE_A, bool RELU>
__global__ __launch_bounds__(256) void gemm_kernel(
    const float* __restrict__ A1, const float* __restrict__ invdeg,
    const float* __restrict__ A2,
    const float* __restrict__ Wl, const float* __restrict__ Wr,
    const float* __restrict__ bias,
    float* __restrict__ out, int N) {
    constexpr int BM = 64, BK = 16;
    constexpr int TN = NC / 16;
    constexpr int KTOT = K1 + K2;
    constexpr int NCHUNK = (KTOT + BK - 1) / BK;

    __shared__ float As[BK][BM + 1];
    __shared__ float Ws[BK][NC];

    const int tid = threadIdx.x;
    const int tx = tid & 15;
    const int ty = tid >> 4;
    const int row0 = blockIdx.x * BM;

    float acc[4][TN];
#pragma unroll
    for (int m = 0; m < 4; m++)
#pragma unroll
        for (int n = 0; n < TN; n++) acc[m][n] = 0.f;

    const int lk = tid & 15;   // k within chunk (coalesced global read)
    const int lm0 = tid >> 4;  // row group

    for (int ch = 0; ch < NCHUNK; ch++) {
        const int k0 = ch * BK;
        // --- A tile (with on-the-fly segment select + invdeg scaling) ---
#pragma unroll
        for (int i = 0; i < 4; i++) {
            int m = lm0 + i * 16;
            int row = row0 + m;
            int kt = k0 + lk;
            float v = 0.f;
            if (row < N) {
                if (kt < K1) {
                    v = A1[(size_t)row * K1 + kt];
                    if (SCALE_A) v *= invdeg[row];
                } else if (K2 > 0 && kt < KTOT) {
                    v = A2[(size_t)row * K2 + (kt - K1)];
                }
            }
            As[lk][m] = v;
        }
        // --- W tile ---
#pragma unroll
        for (int j = 0; j < (BK * NC) / 256; j++) {
            int l = tid + j * 256;
            int kk = l / NC;
            int c = l - kk * NC;
            int kt = k0 + kk;
            float w = 0.f;
            if (kt < K1) w = Wl[kt * NC + c];
            else if (K2 > 0 && kt < KTOT) w = Wr[(kt - K1) * NC + c];
            Ws[kk][c] = w;
        }
        __syncthreads();
#pragma unroll
        for (int k = 0; k < BK; k++) {
            float a[4], b[TN];
#pragma unroll
            for (int m = 0; m < 4; m++) a[m] = As[k][ty * 4 + m];
#pragma unroll
            for (int n = 0; n < TN; n++) b[n] = Ws[k][tx + 16 * n];
#pragma unroll
            for (int m = 0; m < 4; m++)
#pragma unroll
                for (int n = 0; n < TN; n++) acc[m][n] = fmaf(a[m], b[n], acc[m][n]);
        }
        __syncthreads();
    }

#pragma unroll
    for (int m = 0; m < 4; m++) {
        int row = row0 + ty * 4 + m;
        if (row < N) {
#pragma unroll
            for (int n = 0; n < TN; n++) {
                int c = tx + 16 * n;
                float v = acc[m][n] + bias[c];
                if (RELU) v = fmaxf(v, 0.f);
                out[(size_t)row * NC + c] = v;
            }
        }
    }
}

// ---------------------------------------------------------------------------
// BatchNorm (training-mode, biased stats)
// ---------------------------------------------------------------------------
template <int NC>
__global__ void bn_stats_kernel(const float* __restrict__ t, int N,
                                float* __restrict__ gsum, float* __restrict__ gsumsq) {
    int c = threadIdx.x;  // blockDim == NC, coalesced row loads
    float s = 0.f, ss = 0.f;
    for (int r = blockIdx.x; r < N; r += gridDim.x) {
        float v = t[(size_t)r * NC + c];
        s += v;
        ss += v * v;
    }
    atomicAdd(&gsum[c], s);
    atomicAdd(&gsumsq[c], ss);
}

__global__ void bn_finalize_kernel(const float* __restrict__ gsum, const float* __restrict__ gsumsq,
                                   const float* __restrict__ gamma, const float* __restrict__ beta,
                                   float* __restrict__ sc, float* __restrict__ sh,
                                   int NC, float invN) {
    int c = threadIdx.x;
    if (c < NC) {
        float m = gsum[c] * invN;
        float var = gsumsq[c] * invN - m * m;
        float inv = rsqrtf(var + 1e-5f);
        float s = inv * gamma[c];
        sc[c] = s;
        sh[c] = beta[c] - m * s;
    }
}

// in-place z = relu(t*sc + sh), NC = 128
__global__ void bn_relu_kernel(float* __restrict__ t,
                               const float* __restrict__ sc, const float* __restrict__ sh,
                               int n) {
    int i = blockIdx.x * blockDim.x + threadIdx.x;
    if (i < n) {
        int c = i & 127;
        t[i] = fmaxf(fmaf(t[i], sc[c], sh[c]), 0.f);
    }
}

// out[r] = sum_k relu(bn(t2[r,k])) * W3[k] + b3
__global__ void final_kernel(const float* __restrict__ t2,
                             const float* __restrict__ sc, const float* __restrict__ sh,
                             const float* __restrict__ W3, const float* __restrict__ b3,
                             float* __restrict__ out, int N) {
    __shared__ float wv[64], scv[64], shv[64];
    if (threadIdx.x < 64) {
        wv[threadIdx.x] = W3[threadIdx.x];
        scv[threadIdx.x] = sc[threadIdx.x];
        shv[threadIdx.x] = sh[threadIdx.x];
    }
    __syncthreads();
    int r = blockIdx.x * blockDim.x + threadIdx.x;
    if (r >= N) return;
    const float4* row = (const float4*)(t2 + (size_t)r * 64);
    float s = 0.f;
#pragma unroll
    for (int q = 0; q < 16; q++) {
        float4 v = row[q];
        int c = q * 4;
        s += fmaxf(fmaf(v.x, scv[c + 0], shv[c + 0]), 0.f) * wv[c + 0];
        s += fmaxf(fmaf(v.y, scv[c + 1], shv[c + 1]), 0.f) * wv[c + 1];
        s += fmaxf(fmaf(v.z, scv[c + 2], shv[c + 2]), 0.f) * wv[c + 2];
        s += fmaxf(fmaf(v.w, scv[c + 3], shv[c + 3]), 0.f) * wv[c + 3];
    }
    out[r] = s + b3[0];
}

// ---------------------------------------------------------------------------
// launch
// ---------------------------------------------------------------------------
extern "C" void kernel_launch(void* const* d_in, const int* in_sizes, int n_in,
                              void* d_out, int out_size) {
    const float* x   = (const float*)d_in[0];
    const int*   ei  = (const int*)d_in[1];
    const float* Wl1 = (const float*)d_in[2];
    const float* bl1 = (const float*)d_in[3];
    const float* Wr1 = (const float*)d_in[4];
    const float* Wl2 = (const float*)d_in[5];
    const float* bl2 = (const float*)d_in[6];
    const float* Wr2 = (const float*)d_in[7];
    const float* W1  = (const float*)d_in[8];
    const float* b1  = (const float*)d_in[9];
    const float* g1  = (const float*)d_in[10];
    const float* be1 = (const float*)d_in[11];
    const float* W2  = (const float*)d_in[12];
    const float* b2  = (const float*)d_in[13];
    const float* g2  = (const float*)d_in[14];
    const float* be2 = (const float*)d_in[15];
    const float* W3  = (const float*)d_in[16];
    const float* b3  = (const float*)d_in[17];

    const int N = in_sizes[0] / F_IN;
    const int E = in_sizes[1] / 2;
    const int* src = ei;
    const int* dst = ei + E;

    // output layout: out[N] | h1[N,128] | h2[N,128]
    float* out = (float*)d_out;
    float* h1  = out + N;
    float* h2  = h1 + (size_t)N * HID;

    float* base = nullptr;
    cudaGetSymbolAddress((void**)&base, g_scratch);
    float* deg    = base;
    float* invdeg = deg + NMAX;
    float* agg    = invdeg + NMAX;
    float* t1     = agg + (size_t)NMAX * 128;
    float* t2     = t1 + (size_t)NMAX * 128;
    float* sum1   = t2 + (size_t)NMAX * 64;
    float* sumsq1 = sum1 + 128;
    float* sum2   = sumsq1 + 128;
    float* sumsq2 = sum2 + 64;
    float* sc1    = sumsq2 + 64;
    float* sh1    = sc1 + 128;
    float* sc2    = sh1 + 128;
    float* sh2    = sc2 + 64;

    const int TB = 256;
    const int gemm_grid = (N + 63) / 64;

    // ---- init ----
    zero_kernel<<<(N + TB - 1) / TB, TB>>>(deg, N);
    zero_kernel<<<2048, TB>>>(agg, N * 128);
    zero_kernel<<<2, TB>>>(sum1, 384);  // sum1|sumsq1|sum2|sumsq2 contiguous

    // ---- degrees ----
    deg_kernel<<<(E + TB - 1) / TB, TB>>>(dst, deg, E);
    invdeg_kernel<<<(N + TB - 1) / TB, TB>>>(deg, invdeg, N);

    // ---- SAGE layer 1: agg(x) -> h1 = relu(mean@Wl1 + bl1 + x@Wr1) ----
    {
        const int items = E * (F_IN / 4);
        scatter_kernel<F_IN / 4><<<(items + TB - 1) / TB, TB>>>(
            (const float4*)x, src, dst, agg, E);
    }
    gemm_kernel<F_IN, F_IN, HID, true, true><<<gemm_grid, TB>>>(
        agg, invdeg, x, Wl1, Wr1, bl1, h1, N);

    // ---- SAGE layer 2: agg(h1) -> h2 ----
    zero_kernel<<<2048, TB>>>(agg, N * 128);
    {
        const int items = E * (HID / 4);
        scatter_kernel<HID / 4><<<(items + TB - 1) / TB, TB>>>(
            (const float4*)h1, src, dst, agg, E);
    }
    gemm_kernel<HID, HID, HID, true, true><<<gemm_grid, TB>>>(
        agg, invdeg, h1, Wl2, Wr2, bl2, h2, N);

    // ---- MLP layer 1: t1 = h2@W1 + b1; BN stats; z1 = relu(bn(t1)) in-place ----
    gemm_kernel<HID, 0, HID, false, false><<<gemm_grid, TB>>>(
        h2, nullptr, nullptr, W1, nullptr, b1, t1, N);
    bn_stats_kernel<HID><<<256, HID>>>(t1, N, sum1, sumsq1);
    bn_finalize_kernel<<<1, HID>>>(sum1, sumsq1, g1, be1, sc1, sh1, HID, 1.0f / (float)N);
    bn_relu_kernel<<<(N * HID + TB - 1) / TB, TB>>>(t1, sc1, sh1, N * HID);

    // ---- MLP layer 2: t2 = z1@W2 + b2; BN stats ----
    gemm_kernel<HID, 0, H2D, false, false><<<gemm_grid, TB>>>(
        t1, nullptr, nullptr, W2, nullptr, b2, t2, N);
    bn_stats_kernel<H2D><<<256, H2D>>>(t2, N, sum2, sumsq2);
    bn_finalize_kernel<<<1, H2D>>>(sum2, sumsq2, g2, be2, sc2, sh2, H2D, 1.0f / (float)N);

    // ---- final: out = relu(bn(t2)) @ W3 + b3 ----
    final_kernel<<<(N + TB - 1) / TB, TB>>>(t2, sc2, sh2, W3, b3, out, N);
}

// round 2
// speedup vs baseline: 1.3729x; 1.3729x over previous
#include <cuda_runtime.h>
#include <cuda_bf16.h>
#include <cstdint>

// Problem constants (shapes fixed by setup_inputs)
#define NMAX  50000
#define F_IN  100
#define HID   128
#define H2D   64

// Scratch arena: deg | invdeg | agg[N*128] | t1[N*128] | t2[N*64] | bn buffers
__device__ float g_scratch[NMAX * 2 + NMAX * 128 * 2 + NMAX * 64 + 768];

// Split-weight buffers (bf16 hi/lo), transposed [NC][Kpad], zero-padded.
// wl1:128*112 | wr1:128*112 | wl2:128*128 | wr2:128*128 | w1:128*128 | w2:64*128
#define WOFF_L1  0
#define WOFF_R1  14336
#define WOFF_L2  28672
#define WOFF_R2  45056
#define WOFF_M1  61440
#define WOFF_M2  77824
#define WTOTAL   86016
__device__ __nv_bfloat16 g_wh[WTOTAL];
__device__ __nv_bfloat16 g_wl[WTOTAL];

// ---------------------------------------------------------------------------
// utility kernels
// ---------------------------------------------------------------------------
__global__ void zero_kernel(float* __restrict__ p, int n) {
    int i = blockIdx.x * blockDim.x + threadIdx.x;
    for (; i < n; i += gridDim.x * blockDim.x) p[i] = 0.f;
}

__global__ void deg_kernel(const int* __restrict__ dst, float* __restrict__ deg, int E) {
    int e = blockIdx.x * blockDim.x + threadIdx.x;
    if (e < E) atomicAdd(&deg[dst[e]], 1.0f);
}

__global__ void invdeg_kernel(const float* __restrict__ deg, float* __restrict__ invdeg, int N) {
    int i = blockIdx.x * blockDim.x + threadIdx.x;
    if (i < N) invdeg[i] = 1.0f / fmaxf(deg[i], 1.0f);
}

// split + transpose all 6 weight matrices into bf16 hi/lo, [NC][Kpad]
__global__ void prep_weights(const float* __restrict__ Wl1, const float* __restrict__ Wr1,
                             const float* __restrict__ Wl2, const float* __restrict__ Wr2,
                             const float* __restrict__ W1,  const float* __restrict__ W2,
                             __nv_bfloat16* __restrict__ wh, __nv_bfloat16* __restrict__ wl) {
    int i = blockIdx.x * blockDim.x + threadIdx.x;
    if (i >= WTOTAL) return;
    const float* W; int K, KP, NC, local;
    if (i < WOFF_L2) {
        if (i < WOFF_R1) { W = Wl1; local = i; }
        else             { W = Wr1; local = i - WOFF_R1; }
        K = 100; KP = 112; NC = 128;
    } else if (i < WOFF_M2) {
        if (i < WOFF_R2)      { W = Wl2; local = i - WOFF_L2; }
        else if (i < WOFF_M1) { W = Wr2; local = i - WOFF_R2; }
        else                  { W = W1;  local = i - WOFF_M1; }
        K = 128; KP = 128; NC = 128;
    } else {
        W = W2; local = i - WOFF_M2; K = 128; KP = 128; NC = 64;
    }
    int n = local / KP, k = local - n * KP;
    float v = (k < K) ? W[k * NC + n] : 0.f;
    __nv_bfloat16 h = __float2bfloat16_rn(v);
    wh[i] = h;
    wl[i] = __float2bfloat16_rn(v - __bfloat162float(h));
}

// ---------------------------------------------------------------------------
// edge scatter: agg[dst] += x[src], vectorized 16B reduction atomics
// ---------------------------------------------------------------------------
template <int F4>
__global__ void scatter_kernel(const float4* __restrict__ x4,
                               const int* __restrict__ src,
                               const int* __restrict__ dst,
                               float* __restrict__ agg, int E) {
    int idx = blockIdx.x * blockDim.x + threadIdx.x;
    if (idx >= E * F4) return;
    int e = idx / F4;
    int g = idx - e * F4;
    int s = src[e];
    int d = dst[e];
    float4 v = x4[(size_t)s * F4 + g];
    float* p = agg + (size_t)d * (F4 * 4) + g * 4;
    asm volatile("red.global.add.v4.f32 [%0], {%1,%2,%3,%4};"
                 :: "l"(p), "f"(v.x), "f"(v.y), "f"(v.z), "f"(v.w)
                 : "memory");
}

// ---------------------------------------------------------------------------
// Tensor-core GEMM with two-term bf16 splitting (3 MMAs per logical product):
//   out[row,:] = act( (A1[row]*invdeg?) @ B1  +  A2[row] @ B2  + bias )
// B given pre-split/transposed bf16 [NC][KP]. BM=128, BK=16, 256 threads.
// ---------------------------------------------------------------------------
#define MMA_BF16(C, A, B)                                                     \
    asm volatile("mma.sync.aligned.m16n8k16.row.col.f32.bf16.bf16.f32 "       \
                 "{%0,%1,%2,%3}, {%4,%5,%6,%7}, {%8,%9}, {%0,%1,%2,%3};"      \
                 : "+f"((C)[0]), "+f"((C)[1]), "+f"((C)[2]), "+f"((C)[3])     \
                 : "r"((A)[0]), "r"((A)[1]), "r"((A)[2]), "r"((A)[3]),        \
                   "r"((B)[0]), "r"((B)[1]))

template <int K1, int KP1, int K2, int KP2, int NC, bool SCALE, bool RELU>
__global__ __launch_bounds__(256) void mma_gemm(
    const float* __restrict__ A1, const float* __restrict__ invdeg,
    const float* __restrict__ A2,
    const __nv_bfloat16* __restrict__ B1h, const __nv_bfloat16* __restrict__ B1l,
    const __nv_bfloat16* __restrict__ B2h, const __nv_bfloat16* __restrict__ B2l,
    const float* __restrict__ bias, float* __restrict__ out, int N) {

    constexpr int WN = (NC == 128) ? 2 : 1;  // warps along N
    constexpr int WM = 8 / WN;               // warps along M
    constexpr int WARP_M = 128 / WM;         // 32 or 16
    constexpr int MT = WARP_M / 16;          // 2 or 1 m16-tiles per warp
    constexpr int NCW = NC / WN;             // 64 cols per warp
    constexpr int NT = NCW / 8;              // 8 n8-tiles per warp
    constexpr int C1 = KP1 / 16, C2 = KP2 / 16, NCH = C1 + C2;
    constexpr int BW = NC * 8 / 256;         // B words per thread (4 or 2)

    __shared__ __nv_bfloat16 Ah[128][16], Al[128][16];
    __shared__ __nv_bfloat16 Bh[NC][16], Bl[NC][16];

    const int tid = threadIdx.x;
    const int lane = tid & 31;
    const int wid = tid >> 5;
    const int g = lane >> 2;      // groupID
    const int tg = lane & 3;      // thread-in-group
    const int wm = wid / WN;
    const int wn = wid % WN;
    const int row0 = blockIdx.x * 128;

    float c[MT][NT][4];
#pragma unroll
    for (int mt = 0; mt < MT; mt++)
#pragma unroll
        for (int nt = 0; nt < NT; nt++)
#pragma unroll
            for (int q = 0; q < 4; q++) c[mt][nt][q] = 0.f;

    float av[8];
    uint32_t bvh[BW], bvl[BW];

    auto load_chunk = [&](int ch) {
        const float* A;
        const uint32_t *gh, *gl;
        int K, KPW, k0;
        bool sc;
        if (ch < C1) {
            A = A1; K = K1; sc = SCALE;
            gh = (const uint32_t*)B1h; gl = (const uint32_t*)B1l;
            KPW = KP1 / 2; k0 = ch * 16;
        } else {
            A = A2; K = K2; sc = false;
            gh = (const uint32_t*)B2h; gl = (const uint32_t*)B2l;
            KPW = KP2 / 2; k0 = (ch - C1) * 16;
        }
        const int kk = k0 + (tid & 15);
#pragma unroll
        for (int j = 0; j < 8; j++) {
            int m = (tid >> 4) + j * 16;
            int row = row0 + m;
            float v = 0.f;
            if (row < N && kk < K) {
                v = A[(size_t)row * K + kk];
                if (sc) v *= invdeg[row];
            }
            av[j] = v;
        }
#pragma unroll
        for (int j = 0; j < BW; j++) {
            int w = tid + j * 256;
            int n = w >> 3, kp = w & 7;
            bvh[j] = gh[n * KPW + (k0 >> 1) + kp];
            bvl[j] = gl[n * KPW + (k0 >> 1) + kp];
        }
    };

    auto store_chunk = [&]() {
        const int kk = tid & 15;
#pragma unroll
        for (int j = 0; j < 8; j++) {
            int m = (tid >> 4) + j * 16;
            float v = av[j];
            __nv_bfloat16 h = __float2bfloat16_rn(v);
            Ah[m][kk] = h;
            Al[m][kk] = __float2bfloat16_rn(v - __bfloat162float(h));
        }
#pragma unroll
        for (int j = 0; j < BW; j++) {
            int w = tid + j * 256;
            int n = w >> 3, kp = w & 7;
            *(uint32_t*)&Bh[n][kp * 2] = bvh[j];
            *(uint32_t*)&Bl[n][kp * 2] = bvl[j];
        }
    };

    load_chunk(0);
    for (int ch = 0; ch < NCH; ch++) {
        __syncthreads();   // previous chunk's MMA readers done
        store_chunk();
        __syncthreads();
        if (ch + 1 < NCH) load_chunk(ch + 1);  // prefetch overlaps MMA below

        uint32_t fah[MT][4], fal[MT][4], fbh[NT][2], fbl[NT][2];
#pragma unroll
        for (int mt = 0; mt < MT; mt++) {
            int m0 = wm * WARP_M + mt * 16;
            fah[mt][0] = *(const uint32_t*)&Ah[m0 + g][tg * 2];
            fah[mt][1] = *(const uint32_t*)&Ah[m0 + g + 8][tg * 2];
            fah[mt][2] = *(const uint32_t*)&Ah[m0 + g][tg * 2 + 8];
            fah[mt][3] = *(const uint32_t*)&Ah[m0 + g + 8][tg * 2 + 8];
            fal[mt][0] = *(const uint32_t*)&Al[m0 + g][tg * 2];
            fal[mt][1] = *(const uint32_t*)&Al[m0 + g + 8][tg * 2];
            fal[mt][2] = *(const uint32_t*)&Al[m0 + g][tg * 2 + 8];
            fal[mt][3] = *(const uint32_t*)&Al[m0 + g + 8][tg * 2 + 8];
        }
#pragma unroll
        for (int nt = 0; nt < NT; nt++) {
            int n0 = wn * NCW + nt * 8 + g;
            fbh[nt][0] = *(const uint32_t*)&Bh[n0][tg * 2];
            fbh[nt][1] = *(const uint32_t*)&Bh[n0][tg * 2 + 8];
            fbl[nt][0] = *(const uint32_t*)&Bl[n0][tg * 2];
            fbl[nt][1] = *(const uint32_t*)&Bl[n0][tg * 2 + 8];
        }
#pragma unroll
        for (int mt = 0; mt < MT; mt++)
#pragma unroll
            for (int nt = 0; nt < NT; nt++) {
                MMA_BF16(c[mt][nt], fah[mt], fbh[nt]);  // hi*hi
                MMA_BF16(c[mt][nt], fah[mt], fbl[nt]);  // hi*lo
                MMA_BF16(c[mt][nt], fal[mt], fbh[nt]);  // lo*hi
            }
    }

    // epilogue: bias (+ relu), float2 stores
#pragma unroll
    for (int mt = 0; mt < MT; mt++) {
        int rowA = row0 + wm * WARP_M + mt * 16 + g;
        int rowB = rowA + 8;
#pragma unroll
        for (int nt = 0; nt < NT; nt++) {
            int col = wn * NCW + nt * 8 + tg * 2;
            float b0 = bias[col], b1 = bias[col + 1];
            if (rowA < N) {
                float v0 = c[mt][nt][0] + b0;
                float v1 = c[mt][nt][1] + b1;
                if (RELU) { v0 = fmaxf(v0, 0.f); v1 = fmaxf(v1, 0.f); }
                *(float2*)&out[(size_t)rowA * NC + col] = make_float2(v0, v1);
            }
            if (rowB < N) {
                float v2 = c[mt][nt][2] + b0;
                float v3 = c[mt][nt][3] + b1;
                if (RELU) { v2 = fmaxf(v2, 0.f); v3 = fmaxf(v3, 0.f); }
                *(float2*)&out[(size_t)rowB * NC + col] = make_float2(v2, v3);
            }
        }
    }
}

// ---------------------------------------------------------------------------
// BatchNorm (training-mode, biased stats)
// ---------------------------------------------------------------------------
template <int NC>
__global__ void bn_stats_kernel(const float* __restrict__ t, int N,
                                float* __restrict__ gsum, float* __restrict__ gsumsq) {
    int c = threadIdx.x;
    float s = 0.f, ss = 0.f;
    for (int r = blockIdx.x; r < N; r += gridDim.x) {
        float v = t[(size_t)r * NC + c];
        s += v;
        ss += v * v;
    }
    atomicAdd(&gsum[c], s);
    atomicAdd(&gsumsq[c], ss);
}

__global__ void bn_finalize_kernel(const float* __restrict__ gsum, const float* __restrict__ gsumsq,
                                   const float* __restrict__ gamma, const float* __restrict__ beta,
                                   float* __restrict__ sc, float* __restrict__ sh,
                                   int NC, float invN) {
    int c = threadIdx.x;
    if (c < NC) {
        float m = gsum[c] * invN;
        float var = gsumsq[c] * invN - m * m;
        float inv = rsqrtf(var + 1e-5f);
        float s = inv * gamma[c];
        sc[c] = s;
        sh[c] = beta[c] - m * s;
    }
}

__global__ void bn_relu_kernel(float* __restrict__ t,
                               const float* __restrict__ sc, const float* __restrict__ sh,
                               int n) {
    int i = blockIdx.x * blockDim.x + threadIdx.x;
    if (i < n) {
        int c = i & 127;
        t[i] = fmaxf(fmaf(t[i], sc[c], sh[c]), 0.f);
    }
}

__global__ void final_kernel(const float* __restrict__ t2,
                             const float* __restrict__ sc, const float* __restrict__ sh,
                             const float* __restrict__ W3, const float* __restrict__ b3,
                             float* __restrict__ out, int N) {
    __shared__ float wv[64], scv[64], shv[64];
    if (threadIdx.x < 64) {
        wv[threadIdx.x] = W3[threadIdx.x];
        scv[threadIdx.x] = sc[threadIdx.x];
        shv[threadIdx.x] = sh[threadIdx.x];
    }
    __syncthreads();
    int r = blockIdx.x * blockDim.x + threadIdx.x;
    if (r >= N) return;
    const float4* row = (const float4*)(t2 + (size_t)r * 64);
    float s = 0.f;
#pragma unroll
    for (int q = 0; q < 16; q++) {
        float4 v = row[q];
        int c = q * 4;
        s += fmaxf(fmaf(v.x, scv[c + 0], shv[c + 0]), 0.f) * wv[c + 0];
        s += fmaxf(fmaf(v.y, scv[c + 1], shv[c + 1]), 0.f) * wv[c + 1];
        s += fmaxf(fmaf(v.z, scv[c + 2], shv[c + 2]), 0.f) * wv[c + 2];
        s += fmaxf(fmaf(v.w, scv[c + 3], shv[c + 3]), 0.f) * wv[c + 3];
    }
    out[r] = s + b3[0];
}

// ---------------------------------------------------------------------------
// launch
// ---------------------------------------------------------------------------
extern "C" void kernel_launch(void* const* d_in, const int* in_sizes, int n_in,
                              void* d_out, int out_size) {
    const float* x   = (const float*)d_in[0];
    const int*   ei  = (const int*)d_in[1];
    const float* Wl1 = (const float*)d_in[2];
    const float* bl1 = (const float*)d_in[3];
    const float* Wr1 = (const float*)d_in[4];
    const float* Wl2 = (const float*)d_in[5];
    const float* bl2 = (const float*)d_in[6];
    const float* Wr2 = (const float*)d_in[7];
    const float* W1  = (const float*)d_in[8];
    const float* b1  = (const float*)d_in[9];
    const float* g1  = (const float*)d_in[10];
    const float* be1 = (const float*)d_in[11];
    const float* W2  = (const float*)d_in[12];
    const float* b2  = (const float*)d_in[13];
    const float* g2  = (const float*)d_in[14];
    const float* be2 = (const float*)d_in[15];
    const float* W3  = (const float*)d_in[16];
    const float* b3  = (const float*)d_in[17];

    const int N = in_sizes[0] / F_IN;
    const int E = in_sizes[1] / 2;
    const int* src = ei;
    const int* dst = ei + E;

    // output layout: out[N] | h1[N,128] | h2[N,128]
    float* out = (float*)d_out;
    float* h1  = out + N;
    float* h2  = h1 + (size_t)N * HID;

    float* base = nullptr;
    cudaGetSymbolAddress((void**)&base, g_scratch);
    float* deg    = base;
    float* invdeg = deg + NMAX;
    float* agg    = invdeg + NMAX;
    float* t1     = agg + (size_t)NMAX * 128;
    float* t2     = t1 + (size_t)NMAX * 128;
    float* sum1   = t2 + (size_t)NMAX * 64;
    float* sumsq1 = sum1 + 128;
    float* sum2   = sumsq1 + 128;
    float* sumsq2 = sum2 + 64;
    float* sc1    = sumsq2 + 64;
    float* sh1    = sc1 + 128;
    float* sc2    = sh1 + 128;
    float* sh2    = sc2 + 64;

    __nv_bfloat16 *wh = nullptr, *wl = nullptr;
    cudaGetSymbolAddress((void**)&wh, g_wh);
    cudaGetSymbolAddress((void**)&wl, g_wl);

    const int TB = 256;
    const int gemm_grid = (N + 127) / 128;

    // ---- weight prep + init ----
    prep_weights<<<(WTOTAL + TB - 1) / TB, TB>>>(Wl1, Wr1, Wl2, Wr2, W1, W2, wh, wl);
    zero_kernel<<<(N + TB - 1) / TB, TB>>>(deg, N);
    zero_kernel<<<2048, TB>>>(agg, N * 128);
    zero_kernel<<<2, TB>>>(sum1, 384);

    // ---- degrees ----
    deg_kernel<<<(E + TB - 1) / TB, TB>>>(dst, deg, E);
    invdeg_kernel<<<(N + TB - 1) / TB, TB>>>(deg, invdeg, N);

    // ---- SAGE layer 1 ----
    {
        const int items = E * (F_IN / 4);
        scatter_kernel<F_IN / 4><<<(items + TB - 1) / TB, TB>>>(
            (const float4*)x, src, dst, agg, E);
    }
    mma_gemm<100, 112, 100, 112, 128, true, true><<<gemm_grid, TB>>>(
        agg, invdeg, x,
        wh + WOFF_L1, wl + WOFF_L1, wh + WOFF_R1, wl + WOFF_R1,
        bl1, h1, N);

    // ---- SAGE layer 2 ----
    zero_kernel<<<2048, TB>>>(agg, N * 128);
    {
        const int items = E * (HID / 4);
        scatter_kernel<HID / 4><<<(items + TB - 1) / TB, TB>>>(
            (const float4*)h1, src, dst, agg, E);
    }
    mma_gemm<128, 128, 128, 128, 128, true, true><<<gemm_grid, TB>>>(
        agg, invdeg, h1,
        wh + WOFF_L2, wl + WOFF_L2, wh + WOFF_R2, wl + WOFF_R2,
        bl2, h2, N);

    // ---- MLP layer 1: t1 = h2@W1 + b1; BN; relu in place ----
    mma_gemm<128, 128, 0, 0, 128, false, false><<<gemm_grid, TB>>>(
        h2, nullptr, nullptr,
        wh + WOFF_M1, wl + WOFF_M1, wh + WOFF_M1, wl + WOFF_M1,
        b1, t1, N);
    bn_stats_kernel<HID><<<256, HID>>>(t1, N, sum1, sumsq1);
    bn_finalize_kernel<<<1, HID>>>(sum1, sumsq1, g1, be1, sc1, sh1, HID, 1.0f / (float)N);
    bn_relu_kernel<<<(N * HID + TB - 1) / TB, TB>>>(t1, sc1, sh1, N * HID);

    // ---- MLP layer 2: t2 = z1@W2 + b2; BN stats ----
    mma_gemm<128, 128, 0, 0, 64, false, false><<<gemm_grid, TB>>>(
        t1, nullptr, nullptr,
        wh + WOFF_M2, wl + WOFF_M2, wh + WOFF_M2, wl + WOFF_M2,
        b2, t2, N);
    bn_stats_kernel<H2D><<<256, H2D>>>(t2, N, sum2, sumsq2);
    bn_finalize_kernel<<<1, H2D>>>(sum2, sumsq2, g2, be2, sc2, sh2, H2D, 1.0f / (float)N);

    // ---- final ----
    final_kernel<<<(N + TB - 1) / TB, TB>>>(t2, sc2, sh2, W3, b3, out, N);
}

// round 3
// speedup vs baseline: 1.3746x; 1.0012x over previous
#include <cuda_runtime.h>
#include <cuda_bf16.h>
#include <cstdint>

// Problem constants (shapes fixed by setup_inputs)
#define NMAX  50000
#define F_IN  100
#define HID   128
#define H2D   64

// Scratch arena: deg | invdeg | agg[N*128] | t1[N*128] | t2[N*64] | bn buffers
__device__ float g_scratch[NMAX * 2 + NMAX * 128 * 2 + NMAX * 64 + 768];

// Split-weight buffers (bf16 hi/lo), transposed [NC][Kpad], zero-padded.
// wl1:128*112 | wr1:128*112 | wl2:128*128 | wr2:128*128 | w1:128*128 | w2:64*128
#define WOFF_L1  0
#define WOFF_R1  14336
#define WOFF_L2  28672
#define WOFF_R2  45056
#define WOFF_M1  61440
#define WOFF_M2  77824
#define WTOTAL   86016
__device__ __nv_bfloat16 g_wh[WTOTAL];
__device__ __nv_bfloat16 g_wl[WTOTAL];

// ---------------------------------------------------------------------------
// utility kernels
// ---------------------------------------------------------------------------
__global__ void zero_kernel(float* __restrict__ p, int n) {
    int i = blockIdx.x * blockDim.x + threadIdx.x;
    for (; i < n; i += gridDim.x * blockDim.x) p[i] = 0.f;
}

__global__ void deg_kernel(const int* __restrict__ dst, float* __restrict__ deg, int E) {
    int e = blockIdx.x * blockDim.x + threadIdx.x;
    if (e < E) atomicAdd(&deg[dst[e]], 1.0f);
}

__global__ void invdeg_kernel(const float* __restrict__ deg, float* __restrict__ invdeg, int N) {
    int i = blockIdx.x * blockDim.x + threadIdx.x;
    if (i < N) invdeg[i] = 1.0f / fmaxf(deg[i], 1.0f);
}

// split + transpose all 6 weight matrices into bf16 hi/lo, [NC][Kpad]
__global__ void prep_weights(const float* __restrict__ Wl1, const float* __restrict__ Wr1,
                             const float* __restrict__ Wl2, const float* __restrict__ Wr2,
                             const float* __restrict__ W1,  const float* __restrict__ W2,
                             __nv_bfloat16* __restrict__ wh, __nv_bfloat16* __restrict__ wl) {
    int i = blockIdx.x * blockDim.x + threadIdx.x;
    if (i >= WTOTAL) return;
    const float* W; int K, KP, NC, local;
    if (i < WOFF_L2) {
        if (i < WOFF_R1) { W = Wl1; local = i; }
        else             { W = Wr1; local = i - WOFF_R1; }
        K = 100; KP = 112; NC = 128;
    } else if (i < WOFF_M2) {
        if (i < WOFF_R2)      { W = Wl2; local = i - WOFF_L2; }
        else if (i < WOFF_M1) { W = Wr2; local = i - WOFF_R2; }
        else                  { W = W1;  local = i - WOFF_M1; }
        K = 128; KP = 128; NC = 128;
    } else {
        W = W2; local = i - WOFF_M2; K = 128; KP = 128; NC = 64;
    }
    int n = local / KP, k = local - n * KP;
    float v = (k < K) ? W[k * NC + n] : 0.f;
    __nv_bfloat16 h = __float2bfloat16_rn(v);
    wh[i] = h;
    wl[i] = __float2bfloat16_rn(v - __bfloat162float(h));
}

// ---------------------------------------------------------------------------
// edge scatter: agg[dst] += x[src], vectorized 16B reduction atomics
// ---------------------------------------------------------------------------
template <int F4>
__global__ void scatter_kernel(const float4* __restrict__ x4,
                               const int* __restrict__ src,
                               const int* __restrict__ dst,
                               float* __restrict__ agg, int E) {
    int idx = blockIdx.x * blockDim.x + threadIdx.x;
    if (idx >= E * F4) return;
    int e = idx / F4;
    int g = idx - e * F4;
    int s = src[e];
    int d = dst[e];
    float4 v = x4[(size_t)s * F4 + g];
    float* p = agg + (size_t)d * (F4 * 4) + g * 4;
    asm volatile("red.global.add.v4.f32 [%0], {%1,%2,%3,%4};"
                 :: "l"(p), "f"(v.x), "f"(v.y), "f"(v.z), "f"(v.w)
                 : "memory");
}

// ---------------------------------------------------------------------------
// Tensor-core GEMM with two-term bf16 splitting (3 MMAs per logical product):
//   out[row,:] = act( (A1[row]*invdeg?) @ B1  +  A2[row] @ B2  + bias )
// B given pre-split/transposed bf16 [NC][KP]. BM=128, BK=16, 256 threads.
// ---------------------------------------------------------------------------
#define MMA_BF16(C, A, B)                                                     \
    asm volatile("mma.sync.aligned.m16n8k16.row.col.f32.bf16.bf16.f32 "       \
                 "{%0,%1,%2,%3}, {%4,%5,%6,%7}, {%8,%9}, {%0,%1,%2,%3};"      \
                 : "+f"((C)[0]), "+f"((C)[1]), "+f"((C)[2]), "+f"((C)[3])     \
                 : "r"((A)[0]), "r"((A)[1]), "r"((A)[2]), "r"((A)[3]),        \
                   "r"((B)[0]), "r"((B)[1]))

template <int K1, int KP1, int K2, int KP2, int NC, bool SCALE, bool RELU>
__global__ __launch_bounds__(256) void mma_gemm(
    const float* __restrict__ A1, const float* __restrict__ invdeg,
    const float* __restrict__ A2,
    const __nv_bfloat16* __restrict__ B1h, const __nv_bfloat16* __restrict__ B1l,
    const __nv_bfloat16* __restrict__ B2h, const __nv_bfloat16* __restrict__ B2l,
    const float* __restrict__ bias, float* __restrict__ out, int N) {

    constexpr int WN = (NC == 128) ? 2 : 1;  // warps along N
    constexpr int WM = 8 / WN;               // warps along M
    constexpr int WARP_M = 128 / WM;         // 32 or 16
    constexpr int MT = WARP_M / 16;          // 2 or 1 m16-tiles per warp
    constexpr int NCW = NC / WN;             // 64 cols per warp
    constexpr int NT = NCW / 8;              // 8 n8-tiles per warp
    constexpr int C1 = KP1 / 16, C2 = KP2 / 16, NCH = C1 + C2;
    constexpr int BW = NC * 8 / 256;         // B words per thread (4 or 2)

    __shared__ __nv_bfloat16 Ah[128][16], Al[128][16];
    __shared__ __nv_bfloat16 Bh[NC][16], Bl[NC][16];

    const int tid = threadIdx.x;
    const int lane = tid & 31;
    const int wid = tid >> 5;
    const int g = lane >> 2;      // groupID
    const int tg = lane & 3;      // thread-in-group
    const int wm = wid / WN;
    const int wn = wid % WN;
    const int row0 = blockIdx.x * 128;

    float c[MT][NT][4];
#pragma unroll
    for (int mt = 0; mt < MT; mt++)
#pragma unroll
        for (int nt = 0; nt < NT; nt++)
#pragma unroll
            for (int q = 0; q < 4; q++) c[mt][nt][q] = 0.f;

    float av[8];
    uint32_t bvh[BW], bvl[BW];

    auto load_chunk = [&](int ch) {
        const float* A;
        const uint32_t *gh, *gl;
        int K, KPW, k0;
        bool sc;
        if (ch < C1) {
            A = A1; K = K1; sc = SCALE;
            gh = (const uint32_t*)B1h; gl = (const uint32_t*)B1l;
            KPW = KP1 / 2; k0 = ch * 16;
        } else {
            A = A2; K = K2; sc = false;
            gh = (const uint32_t*)B2h; gl = (const uint32_t*)B2l;
            KPW = KP2 / 2; k0 = (ch - C1) * 16;
        }
        const int kk = k0 + (tid & 15);
#pragma unroll
        for (int j = 0; j < 8; j++) {
            int m = (tid >> 4) + j * 16;
            int row = row0 + m;
            float v = 0.f;
            if (row < N && kk < K) {
                v = A[(size_t)row * K + kk];
                if (sc) v *= invdeg[row];
            }
            av[j] = v;
        }
#pragma unroll
        for (int j = 0; j < BW; j++) {
            int w = tid + j * 256;
            int n = w >> 3, kp = w & 7;
            bvh[j] = gh[n * KPW + (k0 >> 1) + kp];
            bvl[j] = gl[n * KPW + (k0 >> 1) + kp];
        }
    };

    auto store_chunk = [&]() {
        const int kk = tid & 15;
#pragma unroll
        for (int j = 0; j < 8; j++) {
            int m = (tid >> 4) + j * 16;
            float v = av[j];
            __nv_bfloat16 h = __float2bfloat16_rn(v);
            Ah[m][kk] = h;
            Al[m][kk] = __float2bfloat16_rn(v - __bfloat162float(h));
        }
#pragma unroll
        for (int j = 0; j < BW; j++) {
            int w = tid + j * 256;
            int n = w >> 3, kp = w & 7;
            *(uint32_t*)&Bh[n][kp * 2] = bvh[j];
            *(uint32_t*)&Bl[n][kp * 2] = bvl[j];
        }
    };

    load_chunk(0);
    for (int ch = 0; ch < NCH; ch++) {
        __syncthreads();   // previous chunk's MMA readers done
        store_chunk();
        __syncthreads();
        if (ch + 1 < NCH) load_chunk(ch + 1);  // prefetch overlaps MMA below

        uint32_t fah[MT][4], fal[MT][4], fbh[NT][2], fbl[NT][2];
#pragma unroll
        for (int mt = 0; mt < MT; mt++) {
            int m0 = wm * WARP_M + mt * 16;
            fah[mt][0] = *(const uint32_t*)&Ah[m0 + g][tg * 2];
            fah[mt][1] = *(const uint32_t*)&Ah[m0 + g + 8][tg * 2];
            fah[mt][2] = *(const uint32_t*)&Ah[m0 + g][tg * 2 + 8];
            fah[mt][3] = *(const uint32_t*)&Ah[m0 + g + 8][tg * 2 + 8];
            fal[mt][0] = *(const uint32_t*)&Al[m0 + g][tg * 2];
            fal[mt][1] = *(const uint32_t*)&Al[m0 + g + 8][tg * 2];
            fal[mt][2] = *(const uint32_t*)&Al[m0 + g][tg * 2 + 8];
            fal[mt][3] = *(const uint32_t*)&Al[m0 + g + 8][tg * 2 + 8];
        }
#pragma unroll
        for (int nt = 0; nt < NT; nt++) {
            int n0 = wn * NCW + nt * 8 + g;
            fbh[nt][0] = *(const uint32_t*)&Bh[n0][tg * 2];
            fbh[nt][1] = *(const uint32_t*)&Bh[n0][tg * 2 + 8];
            fbl[nt][0] = *(const uint32_t*)&Bl[n0][tg * 2];
            fbl[nt][1] = *(const uint32_t*)&Bl[n0][tg * 2 + 8];
        }
#pragma unroll
        for (int mt = 0; mt < MT; mt++)
#pragma unroll
            for (int nt = 0; nt < NT; nt++) {
                MMA_BF16(c[mt][nt], fah[mt], fbh[nt]);  // hi*hi
                MMA_BF16(c[mt][nt], fah[mt], fbl[nt]);  // hi*lo
                MMA_BF16(c[mt][nt], fal[mt], fbh[nt]);  // lo*hi
            }
    }

    // epilogue: bias (+ relu), float2 stores
#pragma unroll
    for (int mt = 0; mt < MT; mt++) {
        int rowA = row0 + wm * WARP_M + mt * 16 + g;
        int rowB = rowA + 8;
#pragma unroll
        for (int nt = 0; nt < NT; nt++) {
            int col = wn * NCW + nt * 8 + tg * 2;
            float b0 = bias[col], b1 = bias[col + 1];
            if (rowA < N) {
                float v0 = c[mt][nt][0] + b0;
                float v1 = c[mt][nt][1] + b1;
                if (RELU) { v0 = fmaxf(v0, 0.f); v1 = fmaxf(v1, 0.f); }
                *(float2*)&out[(size_t)rowA * NC + col] = make_float2(v0, v1);
            }
            if (rowB < N) {
                float v2 = c[mt][nt][2] + b0;
                float v3 = c[mt][nt][3] + b1;
                if (RELU) { v2 = fmaxf(v2, 0.f); v3 = fmaxf(v3, 0.f); }
                *(float2*)&out[(size_t)rowB * NC + col] = make_float2(v2, v3);
            }
        }
    }
}

// ---------------------------------------------------------------------------
// BatchNorm (training-mode, biased stats)
// ---------------------------------------------------------------------------
template <int NC>
__global__ void bn_stats_kernel(const float* __restrict__ t, int N,
                                float* __restrict__ gsum, float* __restrict__ gsumsq) {
    int c = threadIdx.x;
    float s = 0.f, ss = 0.f;
    for (int r = blockIdx.x; r < N; r += gridDim.x) {
        float v = t[(size_t)r * NC + c];
        s += v;
        ss += v * v;
    }
    atomicAdd(&gsum[c], s);
    atomicAdd(&gsumsq[c], ss);
}

__global__ void bn_finalize_kernel(const float* __restrict__ gsum, const float* __restrict__ gsumsq,
                                   const float* __restrict__ gamma, const float* __restrict__ beta,
                                   float* __restrict__ sc, float* __restrict__ sh,
                                   int NC, float invN) {
    int c = threadIdx.x;
    if (c < NC) {
        float m = gsum[c] * invN;
        float var = gsumsq[c] * invN - m * m;
        float inv = rsqrtf(var + 1e-5f);
        float s = inv * gamma[c];
        sc[c] = s;
        sh[c] = beta[c] - m * s;
    }
}

__global__ void bn_relu_kernel(float* __restrict__ t,
                               const float* __restrict__ sc, const float* __restrict__ sh,
                               int n) {
    int i = blockIdx.x * blockDim.x + threadIdx.x;
    if (i < n) {
        int c = i & 127;
        t[i] = fmaxf(fmaf(t[i], sc[c], sh[c]), 0.f);
    }
}

__global__ void final_kernel(const float* __restrict__ t2,
                             const float* __restrict__ sc, const float* __restrict__ sh,
                             const float* __restrict__ W3, const float* __restrict__ b3,
                             float* __restrict__ out, int N) {
    __shared__ float wv[64], scv[64], shv[64];
    if (threadIdx.x < 64) {
        wv[threadIdx.x] = W3[threadIdx.x];
        scv[threadIdx.x] = sc[threadIdx.x];
        shv[threadIdx.x] = sh[threadIdx.x];
    }
    __syncthreads();
    int r = blockIdx.x * blockDim.x + threadIdx.x;
    if (r >= N) return;
    const float4* row = (const float4*)(t2 + (size_t)r * 64);
    float s = 0.f;
#pragma unroll
    for (int q = 0; q < 16; q++) {
        float4 v = row[q];
        int c = q * 4;
        s += fmaxf(fmaf(v.x, scv[c + 0], shv[c + 0]), 0.f) * wv[c + 0];
        s += fmaxf(fmaf(v.y, scv[c + 1], shv[c + 1]), 0.f) * wv[c + 1];
        s += fmaxf(fmaf(v.z, scv[c + 2], shv[c + 2]), 0.f) * wv[c + 2];
        s += fmaxf(fmaf(v.w, scv[c + 3], shv[c + 3]), 0.f) * wv[c + 3];
    }
    out[r] = s + b3[0];
}

// ---------------------------------------------------------------------------
// launch
// ---------------------------------------------------------------------------
extern "C" void kernel_launch(void* const* d_in, const int* in_sizes, int n_in,
                              void* d_out, int out_size) {
    const float* x   = (const float*)d_in[0];
    const int*   ei  = (const int*)d_in[1];
    const float* Wl1 = (const float*)d_in[2];
    const float* bl1 = (const float*)d_in[3];
    const float* Wr1 = (const float*)d_in[4];
    const float* Wl2 = (const float*)d_in[5];
    const float* bl2 = (const float*)d_in[6];
    const float* Wr2 = (const float*)d_in[7];
    const float* W1  = (const float*)d_in[8];
    const float* b1  = (const float*)d_in[9];
    const float* g1  = (const float*)d_in[10];
    const float* be1 = (const float*)d_in[11];
    const float* W2  = (const float*)d_in[12];
    const float* b2  = (const float*)d_in[13];
    const float* g2  = (const float*)d_in[14];
    const float* be2 = (const float*)d_in[15];
    const float* W3  = (const float*)d_in[16];
    const float* b3  = (const float*)d_in[17];

    const int N = in_sizes[0] / F_IN;
    const int E = in_sizes[1] / 2;
    const int* src = ei;
    const int* dst = ei + E;

    // output layout: out[N] | h1[N,128] | h2[N,128]
    float* out = (float*)d_out;
    float* h1  = out + N;
    float* h2  = h1 + (size_t)N * HID;

    float* base = nullptr;
    cudaGetSymbolAddress((void**)&base, g_scratch);
    float* deg    = base;
    float* invdeg = deg + NMAX;
    float* agg    = invdeg + NMAX;
    float* t1     = agg + (size_t)NMAX * 128;
    float* t2     = t1 + (size_t)NMAX * 128;
    float* sum1   = t2 + (size_t)NMAX * 64;
    float* sumsq1 = sum1 + 128;
    float* sum2   = sumsq1 + 128;
    float* sumsq2 = sum2 + 64;
    float* sc1    = sumsq2 + 64;
    float* sh1    = sc1 + 128;
    float* sc2    = sh1 + 128;
    float* sh2    = sc2 + 64;

    __nv_bfloat16 *wh = nullptr, *wl = nullptr;
    cudaGetSymbolAddress((void**)&wh, g_wh);
    cudaGetSymbolAddress((void**)&wl, g_wl);

    const int TB = 256;
    const int gemm_grid = (N + 127) / 128;

    // ---- weight prep + init ----
    prep_weights<<<(WTOTAL + TB - 1) / TB, TB>>>(Wl1, Wr1, Wl2, Wr2, W1, W2, wh, wl);
    zero_kernel<<<(N + TB - 1) / TB, TB>>>(deg, N);
    zero_kernel<<<2048, TB>>>(agg, N * 128);
    zero_kernel<<<2, TB>>>(sum1, 384);

    // ---- degrees ----
    deg_kernel<<<(E + TB - 1) / TB, TB>>>(dst, deg, E);
    invdeg_kernel<<<(N + TB - 1) / TB, TB>>>(deg, invdeg, N);

    // ---- SAGE layer 1 ----
    {
        const int items = E * (F_IN / 4);
        scatter_kernel<F_IN / 4><<<(items + TB - 1) / TB, TB>>>(
            (const float4*)x, src, dst, agg, E);
    }
    mma_gemm<100, 112, 100, 112, 128, true, true><<<gemm_grid, TB>>>(
        agg, invdeg, x,
        wh + WOFF_L1, wl + WOFF_L1, wh + WOFF_R1, wl + WOFF_R1,
        bl1, h1, N);

    // ---- SAGE layer 2 ----
    zero_kernel<<<2048, TB>>>(agg, N * 128);
    {
        const int items = E * (HID / 4);
        scatter_kernel<HID / 4><<<(items + TB - 1) / TB, TB>>>(
            (const float4*)h1, src, dst, agg, E);
    }
    mma_gemm<128, 128, 128, 128, 128, true, true><<<gemm_grid, TB>>>(
        agg, invdeg, h1,
        wh + WOFF_L2, wl + WOFF_L2, wh + WOFF_R2, wl + WOFF_R2,
        bl2, h2, N);

    // ---- MLP layer 1: t1 = h2@W1 + b1; BN; relu in place ----
    mma_gemm<128, 128, 0, 0, 128, false, false><<<gemm_grid, TB>>>(
        h2, nullptr, nullptr,
        wh + WOFF_M1, wl + WOFF_M1, wh + WOFF_M1, wl + WOFF_M1,
        b1, t1, N);
    bn_stats_kernel<HID><<<256, HID>>>(t1, N, sum1, sumsq1);
    bn_finalize_kernel<<<1, HID>>>(sum1, sumsq1, g1, be1, sc1, sh1, HID, 1.0f / (float)N);
    bn_relu_kernel<<<(N * HID + TB - 1) / TB, TB>>>(t1, sc1, sh1, N * HID);

    // ---- MLP layer 2: t2 = z1@W2 + b2; BN stats ----
    mma_gemm<128, 128, 0, 0, 64, false, false><<<gemm_grid, TB>>>(
        t1, nullptr, nullptr,
        wh + WOFF_M2, wl + WOFF_M2, wh + WOFF_M2, wl + WOFF_M2,
        b2, t2, N);
    bn_stats_kernel<H2D><<<256, H2D>>>(t2, N, sum2, sumsq2);
    bn_finalize_kernel<<<1, H2D>>>(sum2, sumsq2, g2, be2, sc2, sh2, H2D, 1.0f / (float)N);

    // ---- final ----
    final_kernel<<<(N + TB - 1) / TB, TB>>>(t2, sc2, sh2, W3, b3, out, N);
}

// round 4
// speedup vs baseline: 1.6048x; 1.1675x over previous
#include <cuda_runtime.h>
#include <cuda_bf16.h>
#include <cstdint>

#define NMAX 50000
#define EMAX 800000
#define F_IN 100
#define HID  128
#define H2D  64

// ---- scratch ----
__device__ int   g_deg[NMAX];
__device__ int   g_off[NMAX + 1];
__device__ int   g_cur[NMAX];
__device__ int   g_csr[EMAX];
// invdeg | agg[N*128] | t1[N*128] | t2[N*64] | bn(768)
__device__ float g_scratch[NMAX * 321 + 768];

// split weights bf16 hi/lo, transposed [NC][Kpad]
#define WOFF_L1  0
#define WOFF_R1  14336
#define WOFF_L2  28672
#define WOFF_R2  45056
#define WOFF_M1  61440
#define WOFF_M2  77824
#define WTOTAL   86016
__device__ __nv_bfloat16 g_wh[WTOTAL];
__device__ __nv_bfloat16 g_wl[WTOTAL];

// ---------------------------------------------------------------------------
__global__ void zero_kernel(float* __restrict__ p, int n) {
    int i = blockIdx.x * blockDim.x + threadIdx.x;
    for (; i < n; i += gridDim.x * blockDim.x) p[i] = 0.f;
}

__global__ void deg_kernel(const int* __restrict__ dst, int* __restrict__ deg, int E) {
    int e = blockIdx.x * blockDim.x + threadIdx.x;
    if (e < E) atomicAdd(&deg[dst[e]], 1);
}

// one-block exclusive scan of deg -> off, cur; also invdeg; off[N] = E
__global__ void scan_kernel(const int* __restrict__ deg, int* __restrict__ off,
                            int* __restrict__ cur, float* __restrict__ invdeg, int N) {
    __shared__ int ssum[1024];
    int t = threadIdx.x;
    int chunk = (N + 1023) >> 10;
    int b = t * chunk;
    int e_ = min(b + chunk, N);
    int s = 0;
    for (int i = b; i < e_; i++) s += deg[i];
    ssum[t] = s;
    __syncthreads();
    for (int d = 1; d < 1024; d <<= 1) {
        int v = (t >= d) ? ssum[t - d] : 0;
        __syncthreads();
        ssum[t] += v;
        __syncthreads();
    }
    int run = (t > 0) ? ssum[t - 1] : 0;
    for (int i = b; i < e_; i++) {
        int dg = deg[i];
        off[i] = run;
        cur[i] = run;
        invdeg[i] = 1.0f / fmaxf((float)dg, 1.0f);
        run += dg;
    }
    if (t == 1023) off[N] = ssum[1023];
}

__global__ void fill_kernel(const int* __restrict__ src, const int* __restrict__ dst,
                            int* __restrict__ cur, int* __restrict__ csr, int E) {
    int e = blockIdx.x * blockDim.x + threadIdx.x;
    if (e < E) {
        int pos = atomicAdd(&cur[dst[e]], 1);
        csr[pos] = src[e];
    }
}

// split + transpose all 6 weight matrices into bf16 hi/lo, [NC][Kpad]
__global__ void prep_weights(const float* __restrict__ Wl1, const float* __restrict__ Wr1,
                             const float* __restrict__ Wl2, const float* __restrict__ Wr2,
                             const float* __restrict__ W1,  const float* __restrict__ W2,
                             __nv_bfloat16* __restrict__ wh, __nv_bfloat16* __restrict__ wl) {
    int i = blockIdx.x * blockDim.x + threadIdx.x;
    if (i >= WTOTAL) return;
    const float* W; int K, KP, NC, local;
    if (i < WOFF_L2) {
        if (i < WOFF_R1) { W = Wl1; local = i; }
        else             { W = Wr1; local = i - WOFF_R1; }
        K = 100; KP = 112; NC = 128;
    } else if (i < WOFF_M2) {
        if (i < WOFF_R2)      { W = Wl2; local = i - WOFF_L2; }
        else if (i < WOFF_M1) { W = Wr2; local = i - WOFF_R2; }
        else                  { W = W1;  local = i - WOFF_M1; }
        K = 128; KP = 128; NC = 128;
    } else {
        W = W2; local = i - WOFF_M2; K = 128; KP = 128; NC = 64;
    }
    int n = local / KP, k = local - n * KP;
    float v = (k < K) ? W[k * NC + n] : 0.f;
    __nv_bfloat16 h = __float2bfloat16_rn(v);
    wh[i] = h;
    wl[i] = __float2bfloat16_rn(v - __bfloat162float(h));
}

// ---------------------------------------------------------------------------
// gather aggregation: warp per dst node, lane owns one float4 feature group;
// writes mean (invdeg folded in). No atomics, no zeroing.
// ---------------------------------------------------------------------------
template <int F4>
__global__ void gather_agg(const float4* __restrict__ x4, const int* __restrict__ csr,
                           const int* __restrict__ off, const float* __restrict__ invdeg,
                           float4* __restrict__ agg, int N) {
    int w = (blockIdx.x * blockDim.x + threadIdx.x) >> 5;
    int lane = threadIdx.x & 31;
    if (w >= N || lane >= F4) return;
    int o = off[w];
    int d = off[w + 1] - o;
    float4 acc = make_float4(0.f, 0.f, 0.f, 0.f);
    int s_next = (d > 0) ? __ldg(&csr[o]) : 0;
    for (int j = 0; j < d; j++) {
        int s = s_next;
        if (j + 1 < d) s_next = __ldg(&csr[o + j + 1]);
        float4 v = __ldg(&x4[(size_t)s * F4 + lane]);
        acc.x += v.x; acc.y += v.y; acc.z += v.z; acc.w += v.w;
    }
    float iv = invdeg[w];
    agg[(size_t)w * F4 + lane] = make_float4(acc.x * iv, acc.y * iv, acc.z * iv, acc.w * iv);
}

// ---------------------------------------------------------------------------
// Tensor-core GEMM, two-term bf16 split (3 MMAs), ldmatrix frags,
// double-buffered smem (1 barrier/chunk), fused BN-relu on A / BN-stats epilogue.
// ---------------------------------------------------------------------------
__device__ __forceinline__ uint32_t smem_u32(const void* p) {
    return (uint32_t)__cvta_generic_to_shared(p);
}

#define LDSM4(R, a)                                                             \
    asm volatile("ldmatrix.sync.aligned.m8n8.x4.shared.b16 {%0,%1,%2,%3}, [%4];"\
                 : "=r"((R)[0]), "=r"((R)[1]), "=r"((R)[2]), "=r"((R)[3])       \
                 : "r"(a))

#define MMA16816(C, A, b0, b1)                                                  \
    asm volatile("mma.sync.aligned.m16n8k16.row.col.f32.bf16.bf16.f32 "         \
                 "{%0,%1,%2,%3}, {%4,%5,%6,%7}, {%8,%9}, {%0,%1,%2,%3};"        \
                 : "+f"((C)[0]), "+f"((C)[1]), "+f"((C)[2]), "+f"((C)[3])       \
                 : "r"((A)[0]), "r"((A)[1]), "r"((A)[2]), "r"((A)[3]),          \
                   "r"(b0), "r"(b1))

template <int K1, int KP1, int K2, int KP2, int NC, bool RELU, bool BNRELU, bool STATS>
__global__ __launch_bounds__(256, 2) void mma_gemm(
    const float* __restrict__ A1, const float* __restrict__ A2,
    const __nv_bfloat16* __restrict__ B1h, const __nv_bfloat16* __restrict__ B1l,
    const __nv_bfloat16* __restrict__ B2h, const __nv_bfloat16* __restrict__ B2l,
    const float* __restrict__ bias,
    const float* __restrict__ bnsc, const float* __restrict__ bnsh,
    float* __restrict__ gsum, float* __restrict__ gsumsq,
    float* __restrict__ out, int N) {

    constexpr int WN = (NC == 128) ? 2 : 1;
    constexpr int WM = 8 / WN;
    constexpr int WARP_M = 128 / WM;       // 32 or 16
    constexpr int MT = WARP_M / 16;        // 2 or 1
    constexpr int NCW = NC / WN;           // 64
    constexpr int NT = NCW / 8;            // 8
    constexpr int C1 = KP1 / 16, C2 = KP2 / 16, NCH = C1 + C2;
    constexpr int BWJ = (NC * 8) / 256;    // uint32 per thread per B array

    __shared__ __align__(16) __nv_bfloat16 Ah[2][128][24], Al[2][128][24];
    __shared__ __align__(16) __nv_bfloat16 Bh[2][NC][24],  Bl[2][NC][24];

    const int tid = threadIdx.x, lane = tid & 31, wid = tid >> 5;
    const int wm = wid / WN, wn = wid % WN;
    const int row0 = blockIdx.x * 128;

    float acc[MT][NT][4];
#pragma unroll
    for (int mt = 0; mt < MT; mt++)
#pragma unroll
        for (int nt = 0; nt < NT; nt++)
#pragma unroll
            for (int q = 0; q < 4; q++) acc[mt][nt][q] = 0.f;

    // staging registers
    float2 av[4];
    uint32_t bsh[BWJ], bsl[BWJ];
    const int kk2 = (tid & 7) * 2;
    const int mr  = tid >> 3;  // 0..31

    auto load_regs = [&](int ch) {
        const float* A; int K, k0, KPW; const uint32_t *gh, *gl; bool bn;
        if (ch < C1) {
            A = A1; K = K1; k0 = ch * 16; KPW = KP1 / 2; bn = BNRELU;
            gh = (const uint32_t*)B1h; gl = (const uint32_t*)B1l;
        } else {
            A = A2; K = K2; k0 = (ch - C1) * 16; KPW = (KP2 > 0 ? KP2 / 2 : 1); bn = false;
            gh = (const uint32_t*)B2h; gl = (const uint32_t*)B2l;
        }
        const int kt = k0 + kk2;
        float s0 = 1.f, h0 = 0.f, s1 = 1.f, h1 = 0.f;
        if (BNRELU && bn) {
            if (kt < K)     { s0 = bnsc[kt];     h0 = bnsh[kt]; }
            if (kt + 1 < K) { s1 = bnsc[kt + 1]; h1 = bnsh[kt + 1]; }
        }
#pragma unroll
        for (int i = 0; i < 4; i++) {
            int row = row0 + mr + i * 32;
            float v0 = 0.f, v1 = 0.f;
            if (row < N) {
                const float* ar = A + (size_t)row * K;
                if (kt + 1 < K) { float2 tv = *(const float2*)(ar + kt); v0 = tv.x; v1 = tv.y; }
                else if (kt < K) { v0 = ar[kt]; }
            }
            if (BNRELU && bn) {
                v0 = fmaxf(fmaf(v0, s0, h0), 0.f);
                v1 = fmaxf(fmaf(v1, s1, h1), 0.f);
            }
            av[i] = make_float2(v0, v1);
        }
#pragma unroll
        for (int j = 0; j < BWJ; j++) {
            int w = tid + j * 256;
            int n = w >> 3, kp = w & 7;
            bsh[j] = gh[n * KPW + (k0 >> 1) + kp];
            bsl[j] = gl[n * KPW + (k0 >> 1) + kp];
        }
    };

    auto store_stage = [&](int st) {
#pragma unroll
        for (int i = 0; i < 4; i++) {
            int m = mr + i * 32;
            float2 v = av[i];
            __nv_bfloat162 h2 = __float22bfloat162_rn(v);
            float2 hf = __bfloat1622float2(h2);
            __nv_bfloat162 l2 = __float22bfloat162_rn(make_float2(v.x - hf.x, v.y - hf.y));
            *(uint32_t*)&Ah[st][m][kk2] = *(uint32_t*)&h2;
            *(uint32_t*)&Al[st][m][kk2] = *(uint32_t*)&l2;
        }
#pragma unroll
        for (int j = 0; j < BWJ; j++) {
            int w = tid + j * 256;
            int n = w >> 3, kp = w & 7;
            *(uint32_t*)&Bh[st][n][kp * 2] = bsh[j];
            *(uint32_t*)&Bl[st][n][kp * 2] = bsl[j];
        }
    };

    const int arow = (lane & 15), acol = ((lane >> 4) << 3);
    const int brow = (lane & 7) + ((lane & 16) >> 1), bcol = (lane & 8);

    load_regs(0);
    store_stage(0);
    __syncthreads();

    for (int ch = 0; ch < NCH; ch++) {
        if (ch + 1 < NCH) load_regs(ch + 1);  // global prefetch hides under MMAs
        const int st = ch & 1;

        uint32_t fah[MT][4], fal[MT][4];
#pragma unroll
        for (int mt = 0; mt < MT; mt++) {
            int m0 = wm * WARP_M + mt * 16;
            LDSM4(fah[mt], smem_u32(&Ah[st][m0 + arow][acol]));
            LDSM4(fal[mt], smem_u32(&Al[st][m0 + arow][acol]));
        }
#pragma unroll
        for (int nh = 0; nh < 2; nh++) {
            uint32_t fbh[2][4], fbl[2][4];
#pragma unroll
            for (int p = 0; p < 2; p++) {
                int n0 = wn * NCW + (nh * 2 + p) * 16;
                LDSM4(fbh[p], smem_u32(&Bh[st][n0 + brow][bcol]));
                LDSM4(fbl[p], smem_u32(&Bl[st][n0 + brow][bcol]));
            }
#pragma unroll
            for (int mt = 0; mt < MT; mt++)
#pragma unroll
                for (int p = 0; p < 2; p++)
#pragma unroll
                    for (int hh = 0; hh < 2; hh++) {
                        int nt = nh * 4 + p * 2 + hh;
                        MMA16816(acc[mt][nt], fah[mt], fbh[p][2 * hh], fbh[p][2 * hh + 1]);
                        MMA16816(acc[mt][nt], fah[mt], fbl[p][2 * hh], fbl[p][2 * hh + 1]);
                        MMA16816(acc[mt][nt], fal[mt], fbh[p][2 * hh], fbh[p][2 * hh + 1]);
                    }
        }
        if (ch + 1 < NCH) store_stage((ch + 1) & 1);
        __syncthreads();
    }

    // ---- epilogue ----
    const int g = lane >> 2, tg = lane & 3;
    float* s_st = reinterpret_cast<float*>(&Ah[0][0][0]);  // 2*NC floats, reuse smem
    if (STATS) {
        for (int i = tid; i < 2 * NC; i += 256) s_st[i] = 0.f;
        __syncthreads();
    }

    float ls[NT][2], lq[NT][2];
    if (STATS) {
#pragma unroll
        for (int nt = 0; nt < NT; nt++) { ls[nt][0] = ls[nt][1] = lq[nt][0] = lq[nt][1] = 0.f; }
    }

#pragma unroll
    for (int mt = 0; mt < MT; mt++) {
        int rowA = row0 + wm * WARP_M + mt * 16 + g;
        int rowB = rowA + 8;
#pragma unroll
        for (int nt = 0; nt < NT; nt++) {
            int col = wn * NCW + nt * 8 + tg * 2;
            float b0 = bias[col], b1 = bias[col + 1];
            float v0 = acc[mt][nt][0] + b0, v1 = acc[mt][nt][1] + b1;
            float v2 = acc[mt][nt][2] + b0, v3 = acc[mt][nt][3] + b1;
            if (RELU) {
                v0 = fmaxf(v0, 0.f); v1 = fmaxf(v1, 0.f);
                v2 = fmaxf(v2, 0.f); v3 = fmaxf(v3, 0.f);
            }
            if (rowA < N) {
                *(float2*)&out[(size_t)rowA * NC + col] = make_float2(v0, v1);
                if (STATS) {
                    ls[nt][0] += v0; lq[nt][0] += v0 * v0;
                    ls[nt][1] += v1; lq[nt][1] += v1 * v1;
                }
            }
            if (rowB < N) {
                *(float2*)&out[(size_t)rowB * NC + col] = make_float2(v2, v3);
                if (STATS) {
                    ls[nt][0] += v2; lq[nt][0] += v2 * v2;
                    ls[nt][1] += v3; lq[nt][1] += v3 * v3;
                }
            }
        }
    }

    if (STATS) {
#pragma unroll
        for (int nt = 0; nt < NT; nt++) {
            int col = wn * NCW + nt * 8 + tg * 2;
            atomicAdd(&s_st[col], ls[nt][0]);
            atomicAdd(&s_st[NC + col], lq[nt][0]);
            atomicAdd(&s_st[col + 1], ls[nt][1]);
            atomicAdd(&s_st[NC + col + 1], lq[nt][1]);
        }
        __syncthreads();
        for (int i = tid; i < NC; i += 256) {
            atomicAdd(&gsum[i], s_st[i]);
            atomicAdd(&gsumsq[i], s_st[NC + i]);
        }
    }
}

// ---------------------------------------------------------------------------
__global__ void bn_finalize_kernel(const float* __restrict__ gsum, const float* __restrict__ gsumsq,
                                   const float* __restrict__ gamma, const float* __restrict__ beta,
                                   float* __restrict__ sc, float* __restrict__ sh,
                                   int NC, float invN) {
    int c = threadIdx.x;
    if (c < NC) {
        float m = gsum[c] * invN;
        float var = gsumsq[c] * invN - m * m;
        float inv = rsqrtf(var + 1e-5f);
        float s = inv * gamma[c];
        sc[c] = s;
        sh[c] = beta[c] - m * s;
    }
}

__global__ void final_kernel(const float* __restrict__ t2,
                             const float* __restrict__ sc, const float* __restrict__ sh,
                             const float* __restrict__ W3, const float* __restrict__ b3,
                             float* __restrict__ out, int N) {
    __shared__ float wv[64], scv[64], shv[64];
    if (threadIdx.x < 64) {
        wv[threadIdx.x] = W3[threadIdx.x];
        scv[threadIdx.x] = sc[threadIdx.x];
        shv[threadIdx.x] = sh[threadIdx.x];
    }
    __syncthreads();
    int r = blockIdx.x * blockDim.x + threadIdx.x;
    if (r >= N) return;
    const float4* row = (const float4*)(t2 + (size_t)r * 64);
    float s = 0.f;
#pragma unroll
    for (int q = 0; q < 16; q++) {
        float4 v = row[q];
        int c = q * 4;
        s += fmaxf(fmaf(v.x, scv[c + 0], shv[c + 0]), 0.f) * wv[c + 0];
        s += fmaxf(fmaf(v.y, scv[c + 1], shv[c + 1]), 0.f) * wv[c + 1];
        s += fmaxf(fmaf(v.z, scv[c + 2], shv[c + 2]), 0.f) * wv[c + 2];
        s += fmaxf(fmaf(v.w, scv[c + 3], shv[c + 3]), 0.f) * wv[c + 3];
    }
    out[r] = s + b3[0];
}

// ---------------------------------------------------------------------------
extern "C" void kernel_launch(void* const* d_in, const int* in_sizes, int n_in,
                              void* d_out, int out_size) {
    const float* x   = (const float*)d_in[0];
    const int*   ei  = (const int*)d_in[1];
    const float* Wl1 = (const float*)d_in[2];
    const float* bl1 = (const float*)d_in[3];
    const float* Wr1 = (const float*)d_in[4];
    const float* Wl2 = (const float*)d_in[5];
    const float* bl2 = (const float*)d_in[6];
    const float* Wr2 = (const float*)d_in[7];
    const float* W1  = (const float*)d_in[8];
    const float* b1  = (const float*)d_in[9];
    const float* g1  = (const float*)d_in[10];
    const float* be1 = (const float*)d_in[11];
    const float* W2  = (const float*)d_in[12];
    const float* b2  = (const float*)d_in[13];
    const float* g2  = (const float*)d_in[14];
    const float* be2 = (const float*)d_in[15];
    const float* W3  = (const float*)d_in[16];
    const float* b3  = (const float*)d_in[17];

    const int N = in_sizes[0] / F_IN;
    const int E = in_sizes[1] / 2;
    const int* src = ei;
    const int* dst = ei + E;

    float* out = (float*)d_out;
    float* h1  = out + N;
    float* h2  = h1 + (size_t)N * HID;

    float* base = nullptr;
    cudaGetSymbolAddress((void**)&base, g_scratch);
    float* invdeg = base;
    float* agg    = invdeg + NMAX;
    float* t1     = agg + (size_t)NMAX * 128;
    float* t2     = t1 + (size_t)NMAX * 128;
    float* sum1   = t2 + (size_t)NMAX * 64;
    float* sumsq1 = sum1 + 128;
    float* sum2   = sumsq1 + 128;
    float* sumsq2 = sum2 + 64;
    float* sc1    = sumsq2 + 64;
    float* sh1    = sc1 + 128;
    float* sc2    = sh1 + 128;
    float* sh2    = sc2 + 64;

    int *deg = nullptr, *off = nullptr, *cur = nullptr, *csr = nullptr;
    cudaGetSymbolAddress((void**)&deg, g_deg);
    cudaGetSymbolAddress((void**)&off, g_off);
    cudaGetSymbolAddress((void**)&cur, g_cur);
    cudaGetSymbolAddress((void**)&csr, g_csr);
    __nv_bfloat16 *wh = nullptr, *wl = nullptr;
    cudaGetSymbolAddress((void**)&wh, g_wh);
    cudaGetSymbolAddress((void**)&wl, g_wl);

    const int TB = 256;
    const int gemm_grid = (N + 127) / 128;
    const int gather_grid = (N * 32 + TB - 1) / TB;

    // prep + init
    prep_weights<<<(WTOTAL + TB - 1) / TB, TB>>>(Wl1, Wr1, Wl2, Wr2, W1, W2, wh, wl);
    zero_kernel<<<(N + TB - 1) / TB, TB>>>((float*)deg, N);  // int zeros == float 0.0 bits
    zero_kernel<<<2, TB>>>(sum1, 384);

    // CSR build
    deg_kernel<<<(E + TB - 1) / TB, TB>>>(dst, deg, E);
    scan_kernel<<<1, 1024>>>(deg, off, cur, invdeg, N);
    fill_kernel<<<(E + TB - 1) / TB, TB>>>(src, dst, cur, csr, E);

    // SAGE layer 1
    gather_agg<F_IN / 4><<<gather_grid, TB>>>((const float4*)x, csr, off, invdeg,
                                              (float4*)agg, N);
    mma_gemm<100, 112, 100, 112, 128, true, false, false><<<gemm_grid, TB>>>(
        agg, x, wh + WOFF_L1, wl + WOFF_L1, wh + WOFF_R1, wl + WOFF_R1,
        bl1, nullptr, nullptr, nullptr, nullptr, h1, N);

    // SAGE layer 2
    gather_agg<HID / 4><<<gather_grid, TB>>>((const float4*)h1, csr, off, invdeg,
                                             (float4*)agg, N);
    mma_gemm<128, 128, 128, 128, 128, true, false, false><<<gemm_grid, TB>>>(
        agg, h1, wh + WOFF_L2, wl + WOFF_L2, wh + WOFF_R2, wl + WOFF_R2,
        bl2, nullptr, nullptr, nullptr, nullptr, h2, N);

    // MLP layer 1: t1 = h2@W1 + b1 (+stats)
    mma_gemm<128, 128, 0, 0, 128, false, false, true><<<gemm_grid, TB>>>(
        h2, h2, wh + WOFF_M1, wl + WOFF_M1, wh + WOFF_M1, wl + WOFF_M1,
        b1, nullptr, nullptr, sum1, sumsq1, t1, N);
    bn_finalize_kernel<<<1, 128>>>(sum1, sumsq1, g1, be1, sc1, sh1, 128, 1.0f / (float)N);

    // MLP layer 2: t2 = relu(bn(t1))@W2 + b2 (BN+relu fused into A load, +stats)
    mma_gemm<128, 128, 0, 0, 64, false, true, true><<<gemm_grid, TB>>>(
        t1, t1, wh + WOFF_M2, wl + WOFF_M2, wh + WOFF_M2, wl + WOFF_M2,
        b2, sc1, sh1, sum2, sumsq2, t2, N);
    bn_finalize_kernel<<<1, 64>>>(sum2, sumsq2, g2, be2, sc2, sh2, 64, 1.0f / (float)N);

    // final
    final_kernel<<<(N + TB - 1) / TB, TB>>>(t2, sc2, sh2, W3, b3, out, N);
}

// round 5
// speedup vs baseline: 1.6596x; 1.0341x over previous
#include <cuda_runtime.h>
#include <cuda_bf16.h>
#include <cstdint>

#define NMAX 50000
#define EMAX 800000
#define F_IN 100
#define HID  128
#define H2D  64

// ---- scratch ----
__device__ int   g_deg[NMAX];
__device__ int   g_off[NMAX + 1];
__device__ int   g_cur[NMAX];
__device__ int   g_csr[EMAX];
// invdeg | agg[N*128] | t1[N*128] | t2[N*64] | bn(768)
__device__ float g_scratch[NMAX * 321 + 768];

// split weights bf16 hi/lo, transposed [NC][Kpad]
#define WOFF_L1  0
#define WOFF_R1  14336
#define WOFF_L2  28672
#define WOFF_R2  45056
#define WOFF_M1  61440
#define WOFF_M2  77824
#define WTOTAL   86016
__device__ __nv_bfloat16 g_wh[WTOTAL];
__device__ __nv_bfloat16 g_wl[WTOTAL];

// ---------------------------------------------------------------------------
__global__ void zero_kernel(int* __restrict__ p, int n) {
    int i = blockIdx.x * blockDim.x + threadIdx.x;
    for (; i < n; i += gridDim.x * blockDim.x) p[i] = 0;
}

__global__ void deg_kernel(const int* __restrict__ dst, int* __restrict__ deg, int E) {
    int e = blockIdx.x * blockDim.x + threadIdx.x;
    if (e < E) atomicAdd(&deg[dst[e]], 1);
}

// one-block exclusive scan of deg -> off, cur; invdeg; zero BN accumulators
__global__ void scan_kernel(const int* __restrict__ deg, int* __restrict__ off,
                            int* __restrict__ cur, float* __restrict__ invdeg,
                            float* __restrict__ bnzero, int N) {
    __shared__ int ssum[1024];
    int t = threadIdx.x;
    if (t < 384) bnzero[t] = 0.f;
    int chunk = (N + 1023) >> 10;
    int b = t * chunk;
    int e_ = min(b + chunk, N);
    int s = 0;
    for (int i = b; i < e_; i++) s += deg[i];
    ssum[t] = s;
    __syncthreads();
    for (int d = 1; d < 1024; d <<= 1) {
        int v = (t >= d) ? ssum[t - d] : 0;
        __syncthreads();
        ssum[t] += v;
        __syncthreads();
    }
    int run = (t > 0) ? ssum[t - 1] : 0;
    for (int i = b; i < e_; i++) {
        int dg = deg[i];
        off[i] = run;
        cur[i] = run;
        invdeg[i] = 1.0f / fmaxf((float)dg, 1.0f);
        run += dg;
    }
    if (t == 1023) off[N] = ssum[1023];
}

__global__ void fill_kernel(const int* __restrict__ src, const int* __restrict__ dst,
                            int* __restrict__ cur, int* __restrict__ csr, int E) {
    int e = blockIdx.x * blockDim.x + threadIdx.x;
    if (e < E) {
        int pos = atomicAdd(&cur[dst[e]], 1);
        csr[pos] = src[e];
    }
}

// split + transpose all 6 weight matrices into bf16 hi/lo, [NC][Kpad]
__global__ void prep_weights(const float* __restrict__ Wl1, const float* __restrict__ Wr1,
                             const float* __restrict__ Wl2, const float* __restrict__ Wr2,
                             const float* __restrict__ W1,  const float* __restrict__ W2,
                             __nv_bfloat16* __restrict__ wh, __nv_bfloat16* __restrict__ wl) {
    int i = blockIdx.x * blockDim.x + threadIdx.x;
    if (i >= WTOTAL) return;
    const float* W; int K, KP, NC, local;
    if (i < WOFF_L2) {
        if (i < WOFF_R1) { W = Wl1; local = i; }
        else             { W = Wr1; local = i - WOFF_R1; }
        K = 100; KP = 112; NC = 128;
    } else if (i < WOFF_M2) {
        if (i < WOFF_R2)      { W = Wl2; local = i - WOFF_L2; }
        else if (i < WOFF_M1) { W = Wr2; local = i - WOFF_R2; }
        else                  { W = W1;  local = i - WOFF_M1; }
        K = 128; KP = 128; NC = 128;
    } else {
        W = W2; local = i - WOFF_M2; K = 128; KP = 128; NC = 64;
    }
    int n = local / KP, k = local - n * KP;
    float v = (k < K) ? W[k * NC + n] : 0.f;
    __nv_bfloat16 h = __float2bfloat16_rn(v);
    wh[i] = h;
    wl[i] = __float2bfloat16_rn(v - __bfloat162float(h));
}

// ---------------------------------------------------------------------------
// gather aggregation: warp per dst node, lane owns one float4 feature group.
// ---------------------------------------------------------------------------
template <int F4>
__global__ void gather_agg(const float4* __restrict__ x4, const int* __restrict__ csr,
                           const int* __restrict__ off, const float* __restrict__ invdeg,
                           float4* __restrict__ agg, int N) {
    int w = (blockIdx.x * blockDim.x + threadIdx.x) >> 5;
    int lane = threadIdx.x & 31;
    if (w >= N || lane >= F4) return;
    int o = off[w];
    int d = off[w + 1] - o;
    float4 acc = make_float4(0.f, 0.f, 0.f, 0.f);
    int j = 0;
    for (; j + 2 <= d; j += 2) {
        int s0 = __ldg(&csr[o + j]);
        int s1 = __ldg(&csr[o + j + 1]);
        float4 v0 = __ldg(&x4[(size_t)s0 * F4 + lane]);
        float4 v1 = __ldg(&x4[(size_t)s1 * F4 + lane]);
        acc.x += v0.x; acc.y += v0.y; acc.z += v0.z; acc.w += v0.w;
        acc.x += v1.x; acc.y += v1.y; acc.z += v1.z; acc.w += v1.w;
    }
    if (j < d) {
        int s0 = __ldg(&csr[o + j]);
        float4 v0 = __ldg(&x4[(size_t)s0 * F4 + lane]);
        acc.x += v0.x; acc.y += v0.y; acc.z += v0.z; acc.w += v0.w;
    }
    float iv = invdeg[w];
    agg[(size_t)w * F4 + lane] = make_float4(acc.x * iv, acc.y * iv, acc.z * iv, acc.w * iv);
}

// ---------------------------------------------------------------------------
// Tensor-core GEMM, two-term bf16 split (3 MMAs), ldmatrix frags,
// double-buffered smem, cp.async for B tiles, register-staged A conversion.
// ---------------------------------------------------------------------------
__device__ __forceinline__ uint32_t smem_u32(const void* p) {
    return (uint32_t)__cvta_generic_to_shared(p);
}

#define LDSM4(R, a)                                                             \
    asm volatile("ldmatrix.sync.aligned.m8n8.x4.shared.b16 {%0,%1,%2,%3}, [%4];"\
                 : "=r"((R)[0]), "=r"((R)[1]), "=r"((R)[2]), "=r"((R)[3])       \
                 : "r"(a))

#define MMA16816(C, A, b0, b1)                                                  \
    asm volatile("mma.sync.aligned.m16n8k16.row.col.f32.bf16.bf16.f32 "         \
                 "{%0,%1,%2,%3}, {%4,%5,%6,%7}, {%8,%9}, {%0,%1,%2,%3};"        \
                 : "+f"((C)[0]), "+f"((C)[1]), "+f"((C)[2]), "+f"((C)[3])       \
                 : "r"((A)[0]), "r"((A)[1]), "r"((A)[2]), "r"((A)[3]),          \
                   "r"(b0), "r"(b1))

#define CP_ASYNC16(smem_addr, gptr)                                             \
    asm volatile("cp.async.ca.shared.global [%0], [%1], 16;"                    \
                 :: "r"(smem_addr), "l"(gptr) : "memory")

template <int K1, int KP1, int K2, int KP2, int NC, bool RELU, bool BNRELU, bool STATS>
__global__ __launch_bounds__(256, 2) void mma_gemm(
    const float* __restrict__ A1, const float* __restrict__ A2,
    const __nv_bfloat16* __restrict__ B1h, const __nv_bfloat16* __restrict__ B1l,
    const __nv_bfloat16* __restrict__ B2h, const __nv_bfloat16* __restrict__ B2l,
    const float* __restrict__ bias,
    const float* __restrict__ bnsc, const float* __restrict__ bnsh,
    float* __restrict__ gsum, float* __restrict__ gsumsq,
    float* __restrict__ out, int N) {

    constexpr int WN = (NC == 128) ? 2 : 1;
    constexpr int WM = 8 / WN;
    constexpr int WARP_M = 128 / WM;       // 32 or 16
    constexpr int MT = WARP_M / 16;        // 2 or 1
    constexpr int NCW = NC / WN;           // 64
    constexpr int NT = NCW / 8;            // 8
    constexpr int C1 = KP1 / 16, C2 = KP2 / 16, NCH = C1 + C2;
    constexpr int BCP = NC * 2;            // 16B chunks per B array per stage

    __shared__ __align__(16) __nv_bfloat16 Ah[2][128][24], Al[2][128][24];
    __shared__ __align__(16) __nv_bfloat16 Bh[2][NC][24],  Bl[2][NC][24];

    const int tid = threadIdx.x, lane = tid & 31, wid = tid >> 5;
    const int wm = wid / WN, wn = wid % WN;
    const int row0 = blockIdx.x * 128;

    float acc[MT][NT][4];
#pragma unroll
    for (int mt = 0; mt < MT; mt++)
#pragma unroll
        for (int nt = 0; nt < NT; nt++)
#pragma unroll
            for (int q = 0; q < 4; q++) acc[mt][nt][q] = 0.f;

    float2 av[4];                 // A staging (needs fp32->bf16 split conversion)
    const int kk2 = (tid & 7) * 2;
    const int mr  = tid >> 3;     // 0..31

    // B cp.async mapping: chunk w in [0, BCP): row n = w>>1, half = w&1
    auto issue_B = [&](int ch, int st) {
        const __nv_bfloat16 *gh, *gl; int KPE, k0;
        if (ch < C1) { gh = B1h; gl = B1l; KPE = KP1; k0 = ch * 16; }
        else         { gh = B2h; gl = B2l; KPE = KP2; k0 = (ch - C1) * 16; }
#pragma unroll
        for (int j = 0; j < (BCP + 255) / 256; j++) {
            int w = tid + j * 256;
            if (BCP < 256 && w >= BCP) break;
            int n = w >> 1, half = w & 1;
            const __nv_bfloat16* srch = gh + n * KPE + k0 + half * 8;
            const __nv_bfloat16* srcl = gl + n * KPE + k0 + half * 8;
            CP_ASYNC16(smem_u32(&Bh[st][n][half * 8]), srch);
            CP_ASYNC16(smem_u32(&Bl[st][n][half * 8]), srcl);
        }
        asm volatile("cp.async.commit_group;" ::: "memory");
    };

    auto load_A = [&](int ch) {
        const float* A; int K, k0; bool bn;
        if (ch < C1) { A = A1; K = K1; k0 = ch * 16; bn = BNRELU; }
        else         { A = A2; K = K2; k0 = (ch - C1) * 16; bn = false; }
        const int kt = k0 + kk2;
        float s0 = 1.f, h0 = 0.f, s1 = 1.f, h1 = 0.f;
        if (BNRELU && bn) {
            if (kt < K)     { s0 = bnsc[kt];     h0 = bnsh[kt]; }
            if (kt + 1 < K) { s1 = bnsc[kt + 1]; h1 = bnsh[kt + 1]; }
        }
#pragma unroll
        for (int i = 0; i < 4; i++) {
            int row = row0 + mr + i * 32;
            float v0 = 0.f, v1 = 0.f;
            if (row < N) {
                const float* ar = A + (size_t)row * K;
                if (kt + 1 < K) { float2 tv = *(const float2*)(ar + kt); v0 = tv.x; v1 = tv.y; }
                else if (kt < K) { v0 = ar[kt]; }
            }
            if (BNRELU && bn) {
                v0 = fmaxf(fmaf(v0, s0, h0), 0.f);
                v1 = fmaxf(fmaf(v1, s1, h1), 0.f);
            }
            av[i] = make_float2(v0, v1);
        }
    };

    auto store_A = [&](int st) {
#pragma unroll
        for (int i = 0; i < 4; i++) {
            int m = mr + i * 32;
            float2 v = av[i];
            __nv_bfloat162 h2 = __float22bfloat162_rn(v);
            float2 hf = __bfloat1622float2(h2);
            __nv_bfloat162 l2 = __float22bfloat162_rn(make_float2(v.x - hf.x, v.y - hf.y));
            *(uint32_t*)&Ah[st][m][kk2] = *(uint32_t*)&h2;
            *(uint32_t*)&Al[st][m][kk2] = *(uint32_t*)&l2;
        }
    };

    const int arow = (lane & 15), acol = ((lane >> 4) << 3);
    const int brow = (lane & 7) + ((lane & 16) >> 1), bcol = (lane & 8);

    // prologue: fill stage 0
    issue_B(0, 0);
    load_A(0);
    store_A(0);
    asm volatile("cp.async.wait_group 0;" ::: "memory");
    __syncthreads();

    for (int ch = 0; ch < NCH; ch++) {
        const int st = ch & 1;
        if (ch + 1 < NCH) {
            issue_B(ch + 1, st ^ 1);  // async, lands during MMAs
            load_A(ch + 1);           // global loads in flight during MMAs
        }

        uint32_t fah[MT][4], fal[MT][4];
#pragma unroll
        for (int mt = 0; mt < MT; mt++) {
            int m0 = wm * WARP_M + mt * 16;
            LDSM4(fah[mt], smem_u32(&Ah[st][m0 + arow][acol]));
            LDSM4(fal[mt], smem_u32(&Al[st][m0 + arow][acol]));
        }
#pragma unroll
        for (int nh = 0; nh < 2; nh++) {
            uint32_t fbh[2][4], fbl[2][4];
#pragma unroll
            for (int p = 0; p < 2; p++) {
                int n0 = wn * NCW + (nh * 2 + p) * 16;
                LDSM4(fbh[p], smem_u32(&Bh[st][n0 + brow][bcol]));
                LDSM4(fbl[p], smem_u32(&Bl[st][n0 + brow][bcol]));
            }
#pragma unroll
            for (int mt = 0; mt < MT; mt++)
#pragma unroll
                for (int p = 0; p < 2; p++)
#pragma unroll
                    for (int hh = 0; hh < 2; hh++) {
                        int nt = nh * 4 + p * 2 + hh;
                        MMA16816(acc[mt][nt], fah[mt], fbh[p][2 * hh], fbh[p][2 * hh + 1]);
                        MMA16816(acc[mt][nt], fah[mt], fbl[p][2 * hh], fbl[p][2 * hh + 1]);
                        MMA16816(acc[mt][nt], fal[mt], fbh[p][2 * hh], fbh[p][2 * hh + 1]);
                    }
        }
        if (ch + 1 < NCH) {
            store_A(st ^ 1);
            asm volatile("cp.async.wait_group 0;" ::: "memory");
        }
        __syncthreads();
    }

    // ---- epilogue ----
    const int g = lane >> 2, tg = lane & 3;
    float* s_st = reinterpret_cast<float*>(&Ah[0][0][0]);  // reuse smem
    if (STATS) {
        for (int i = tid; i < 2 * NC; i += 256) s_st[i] = 0.f;
        __syncthreads();
    }

    float ls[NT][2], lq[NT][2];
    if (STATS) {
#pragma unroll
        for (int nt = 0; nt < NT; nt++) { ls[nt][0] = ls[nt][1] = lq[nt][0] = lq[nt][1] = 0.f; }
    }

#pragma unroll
    for (int mt = 0; mt < MT; mt++) {
        int rowA = row0 + wm * WARP_M + mt * 16 + g;
        int rowB = rowA + 8;
#pragma unroll
        for (int nt = 0; nt < NT; nt++) {
            int col = wn * NCW + nt * 8 + tg * 2;
            float b0 = bias[col], b1 = bias[col + 1];
            float v0 = acc[mt][nt][0] + b0, v1 = acc[mt][nt][1] + b1;
            float v2 = acc[mt][nt][2] + b0, v3 = acc[mt][nt][3] + b1;
            if (RELU) {
                v0 = fmaxf(v0, 0.f); v1 = fmaxf(v1, 0.f);
                v2 = fmaxf(v2, 0.f); v3 = fmaxf(v3, 0.f);
            }
            if (rowA < N) {
                *(float2*)&out[(size_t)rowA * NC + col] = make_float2(v0, v1);
                if (STATS) {
                    ls[nt][0] += v0; lq[nt][0] += v0 * v0;
                    ls[nt][1] += v1; lq[nt][1] += v1 * v1;
                }
            }
            if (rowB < N) {
                *(float2*)&out[(size_t)rowB * NC + col] = make_float2(v2, v3);
                if (STATS) {
                    ls[nt][0] += v2; lq[nt][0] += v2 * v2;
                    ls[nt][1] += v3; lq[nt][1] += v3 * v3;
                }
            }
        }
    }

    if (STATS) {
#pragma unroll
        for (int nt = 0; nt < NT; nt++) {
            int col = wn * NCW + nt * 8 + tg * 2;
            atomicAdd(&s_st[col], ls[nt][0]);
            atomicAdd(&s_st[NC + col], lq[nt][0]);
            atomicAdd(&s_st[col + 1], ls[nt][1]);
            atomicAdd(&s_st[NC + col + 1], lq[nt][1]);
        }
        __syncthreads();
        for (int i = tid; i < NC; i += 256) {
            atomicAdd(&gsum[i], s_st[i]);
            atomicAdd(&gsumsq[i], s_st[NC + i]);
        }
    }
}

// ---------------------------------------------------------------------------
__global__ void bn_finalize_kernel(const float* __restrict__ gsum, const float* __restrict__ gsumsq,
                                   const float* __restrict__ gamma, const float* __restrict__ beta,
                                   float* __restrict__ sc, float* __restrict__ sh,
                                   int NC, float invN) {
    int c = threadIdx.x;
    if (c < NC) {
        float m = gsum[c] * invN;
        float var = gsumsq[c] * invN - m * m;
        float inv = rsqrtf(var + 1e-5f);
        float s = inv * gamma[c];
        sc[c] = s;
        sh[c] = beta[c] - m * s;
    }
}

__global__ void final_kernel(const float* __restrict__ t2,
                             const float* __restrict__ sc, const float* __restrict__ sh,
                             const float* __restrict__ W3, const float* __restrict__ b3,
                             float* __restrict__ out, int N) {
    __shared__ float wv[64], scv[64], shv[64];
    if (threadIdx.x < 64) {
        wv[threadIdx.x] = W3[threadIdx.x];
        scv[threadIdx.x] = sc[threadIdx.x];
        shv[threadIdx.x] = sh[threadIdx.x];
    }
    __syncthreads();
    int r = blockIdx.x * blockDim.x + threadIdx.x;
    if (r >= N) return;
    const float4* row = (const float4*)(t2 + (size_t)r * 64);
    float s = 0.f;
#pragma unroll
    for (int q = 0; q < 16; q++) {
        float4 v = row[q];
        int c = q * 4;
        s += fmaxf(fmaf(v.x, scv[c + 0], shv[c + 0]), 0.f) * wv[c + 0];
        s += fmaxf(fmaf(v.y, scv[c + 1], shv[c + 1]), 0.f) * wv[c + 1];
        s += fmaxf(fmaf(v.z, scv[c + 2], shv[c + 2]), 0.f) * wv[c + 2];
        s += fmaxf(fmaf(v.w, scv[c + 3], shv[c + 3]), 0.f) * wv[c + 3];
    }
    out[r] = s + b3[0];
}

// ---------------------------------------------------------------------------
extern "C" void kernel_launch(void* const* d_in, const int* in_sizes, int n_in,
                              void* d_out, int out_size) {
    const float* x   = (const float*)d_in[0];
    const int*   ei  = (const int*)d_in[1];
    const float* Wl1 = (const float*)d_in[2];
    const float* bl1 = (const float*)d_in[3];
    const float* Wr1 = (const float*)d_in[4];
    const float* Wl2 = (const float*)d_in[5];
    const float* bl2 = (const float*)d_in[6];
    const float* Wr2 = (const float*)d_in[7];
    const float* W1  = (const float*)d_in[8];
    const float* b1  = (const float*)d_in[9];
    const float* g1  = (const float*)d_in[10];
    const float* be1 = (const float*)d_in[11];
    const float* W2  = (const float*)d_in[12];
    const float* b2  = (const float*)d_in[13];
    const float* g2  = (const float*)d_in[14];
    const float* be2 = (const float*)d_in[15];
    const float* W3  = (const float*)d_in[16];
    const float* b3  = (const float*)d_in[17];

    const int N = in_sizes[0] / F_IN;
    const int E = in_sizes[1] / 2;
    const int* src = ei;
    const int* dst = ei + E;

    float* out = (float*)d_out;
    float* h1  = out + N;
    float* h2  = h1 + (size_t)N * HID;

    float* base = nullptr;
    cudaGetSymbolAddress((void**)&base, g_scratch);
    float* invdeg = base;
    float* agg    = invdeg + NMAX;
    float* t1     = agg + (size_t)NMAX * 128;
    float* t2     = t1 + (size_t)NMAX * 128;
    float* sum1   = t2 + (size_t)NMAX * 64;
    float* sumsq1 = sum1 + 128;
    float* sum2   = sumsq1 + 128;
    float* sumsq2 = sum2 + 64;
    float* sc1    = sumsq2 + 64;
    float* sh1    = sc1 + 128;
    float* sc2    = sh1 + 128;
    float* sh2    = sc2 + 64;

    int *deg = nullptr, *off = nullptr, *cur = nullptr, *csr = nullptr;
    cudaGetSymbolAddress((void**)&deg, g_deg);
    cudaGetSymbolAddress((void**)&off, g_off);
    cudaGetSymbolAddress((void**)&cur, g_cur);
    cudaGetSymbolAddress((void**)&csr, g_csr);
    __nv_bfloat16 *wh = nullptr, *wl = nullptr;
    cudaGetSymbolAddress((void**)&wh, g_wh);
    cudaGetSymbolAddress((void**)&wl, g_wl);

    const int TB = 256;
    const int gemm_grid = (N + 127) / 128;
    const int gather_grid = (N * 32 + TB - 1) / TB;

    // prep + init
    prep_weights<<<(WTOTAL + TB - 1) / TB, TB>>>(Wl1, Wr1, Wl2, Wr2, W1, W2, wh, wl);
    zero_kernel<<<(N + TB - 1) / TB, TB>>>(deg, N);

    // CSR build (scan also zeroes the 384 BN accumulators)
    deg_kernel<<<(E + TB - 1) / TB, TB>>>(dst, deg, E);
    scan_kernel<<<1, 1024>>>(deg, off, cur, invdeg, sum1, N);
    fill_kernel<<<(E + TB - 1) / TB, TB>>>(src, dst, cur, csr, E);

    // SAGE layer 1
    gather_agg<F_IN / 4><<<gather_grid, TB>>>((const float4*)x, csr, off, invdeg,
                                              (float4*)agg, N);
    mma_gemm<100, 112, 100, 112, 128, true, false, false><<<gemm_grid, TB>>>(
        agg, x, wh + WOFF_L1, wl + WOFF_L1, wh + WOFF_R1, wl + WOFF_R1,
        bl1, nullptr, nullptr, nullptr, nullptr, h1, N);

    // SAGE layer 2
    gather_agg<HID / 4><<<gather_grid, TB>>>((const float4*)h1, csr, off, invdeg,
                                             (float4*)agg, N);
    mma_gemm<128, 128, 128, 128, 128, true, false, false><<<gemm_grid, TB>>>(
        agg, h1, wh + WOFF_L2, wl + WOFF_L2, wh + WOFF_R2, wl + WOFF_R2,
        bl2, nullptr, nullptr, nullptr, nullptr, h2, N);

    // MLP layer 1: t1 = h2@W1 + b1 (+stats)
    mma_gemm<128, 128, 0, 0, 128, false, false, true><<<gemm_grid, TB>>>(
        h2, h2, wh + WOFF_M1, wl + WOFF_M1, wh + WOFF_M1, wl + WOFF_M1,
        b1, nullptr, nullptr, sum1, sumsq1, t1, N);
    bn_finalize_kernel<<<1, 128>>>(sum1, sumsq1, g1, be1, sc1, sh1, 128, 1.0f / (float)N);

    // MLP layer 2: t2 = relu(bn(t1))@W2 + b2 (BN+relu fused into A load, +stats)
    mma_gemm<128, 128, 0, 0, 64, false, true, true><<<gemm_grid, TB>>>(
        t1, t1, wh + WOFF_M2, wl + WOFF_M2, wh + WOFF_M2, wl + WOFF_M2,
        b2, sc1, sh1, sum2, sumsq2, t2, N);
    bn_finalize_kernel<<<1, 64>>>(sum2, sumsq2, g2, be2, sc2, sh2, 64, 1.0f / (float)N);

    // final
    final_kernel<<<(N + TB - 1) / TB, TB>>>(t2, sc2, sh2, W3, b3, out, N);
}